// round 8
// baseline (speedup 1.0000x reference)
#include <cuda_runtime.h>

#define NT 512
#define SCALEF 0.17677669529663687f   // 1/sqrt(32)

// smem strides (floats). A-operand frag pattern needs LD%32 in {4,12,20,28};
// B-operand frag pattern needs LD%32 == 8. All even for float2 stores.
#define SX_LD 100   // x / attn_out  (A): 100%32=4
#define SQ_LD 100   // q             (A): 4
#define SA_LD 108   // scores/probs  (A): 108%32=12
#define KT_LD 104   // kT (tf32)     (B): 104%32=8
#define SV_LD 104   // v  (tf32)     (B): 8
#define SW_LD 40    // weight chunk  (B): 40%32=8

// region offsets (floats)
#define OFF_SX 0        // [112][100] = 11200
#define OFF_SQ 11200    // [112][100] = 11200
#define OFF_KT 22400    // [96][104]  = 9984
#define OFF_SV 32384    // [104][104] = 10816
#define OFF_SA 43200    // [112][108] = 12096  (union: wh/wl below)
#define OFF_WH 43200    // [96][40] = 3840
#define OFF_WL 47040    // [96][40] = 3840
#define OFF_RI 55296    // 112
#define SMEM_FLOATS 55408
#define SMEM_BYTES (SMEM_FLOATS * 4)   // 221,632 B

__device__ float g_wqkvT[96 * 288];    // wT[c][j] = qkv_w[j*96+c]
__device__ float g_wprojT[96 * 96];    // wT[c][j] = proj_w[j*96+c]
__device__ float g_bias[3 * 98 * 100]; // bias[h][n][m], m padded to 100 (pad=0)

// ---- tf32 helpers ----
__device__ __forceinline__ unsigned t32(float f) {
    unsigned u; asm("cvt.rna.tf32.f32 %0, %1;" : "=r"(u) : "f"(f)); return u;
}
__device__ __forceinline__ void split2(float f, unsigned& hi, unsigned& lo) {
    hi = t32(f);
    lo = t32(f - __uint_as_float(hi));
}
// D += A(16x8,row) * B(8x8,col), tf32 inputs, f32 accum
__device__ __forceinline__ void mma8(float4& d, const unsigned a[4], unsigned b0, unsigned b1) {
    asm volatile(
        "mma.sync.aligned.m16n8k8.row.col.f32.tf32.tf32.f32 "
        "{%0,%1,%2,%3},{%4,%5,%6,%7},{%8,%9},{%0,%1,%2,%3};"
        : "+f"(d.x), "+f"(d.y), "+f"(d.z), "+f"(d.w)
        : "r"(a[0]), "r"(a[1]), "r"(a[2]), "r"(a[3]), "r"(b0), "r"(b1));
}

// ---- prep: transposed weights + padded bias ----
__global__ void prep_kernel(const float* __restrict__ qkv_w,
                            const float* __restrict__ proj_w,
                            const float* __restrict__ table,
                            const int* __restrict__ rel)
{
    int i = blockIdx.x * blockDim.x + threadIdx.x;
    if (i < 96 * 288) {
        int c = i / 288, j = i - c * 288;
        g_wqkvT[i] = qkv_w[j * 96 + c];
    } else if (i < 96 * 288 + 96 * 96) {
        int k = i - 96 * 288;
        int c = k / 96, j = k - c * 96;
        g_wprojT[k] = proj_w[j * 96 + c];
    } else if (i < 96 * 288 + 96 * 96 + 3 * 98 * 100) {
        int k = i - (96 * 288 + 96 * 96);
        int h = k / 9800, r = k - h * 9800;
        int n = r / 100, m = r - n * 100;
        g_bias[k] = (m < 98) ? table[rel[n * 98 + m] * 3 + h] : 0.f;
    }
}

__global__ void __launch_bounds__(NT, 1)
wa3d_main(const float* __restrict__ x, const float* __restrict__ qkv_b,
          const float* __restrict__ proj_b, float* __restrict__ out)
{
    extern __shared__ float sm[];
    float* sx = sm + OFF_SX;   // x, later attention output
    float* sq = sm + OFF_SQ;   // q (fp32)
    float* kt = sm + OFF_KT;   // kT (tf32 bits), [d 96][m 104]
    float* sv = sm + OFF_SV;   // v  (tf32 bits), [m 104][d 104]
    float* sa = sm + OFF_SA;   // scores/probs fp32
    float* wh = sm + OFF_WH;   // weight chunk hi (union with sa)
    float* wl = sm + OFF_WL;   // weight chunk lo (union with sa)
    float* ri = sm + OFF_RI;   // 1/rowsum

    const int b    = blockIdx.x;
    const int tid  = threadIdx.x;
    const int warp = tid >> 5, lane = tid & 31;
    const int gid  = lane >> 2;   // 0..7
    const int tig  = lane & 3;    // 0..3

    // ---- full smem zero (all padded/garbage reads become exactly 0) ----
    for (int i = tid; i < SMEM_FLOATS; i += NT) sm[i] = 0.f;
    __syncthreads();

    // ---- stage x[b] ----
    const float* xb = x + (size_t)b * 9408;
    for (int i = tid; i < 9408; i += NT) {
        int r = i / 96, c = i - r * 96;
        sx[r * SX_LD + c] = xb[i];
    }
    // (sync provided by first chunk's staging sync below)

    // ============ GEMM1: qkv = x @ qkv_w^T + b  (9 chunks of 32 cols) ============
    for (int ch = 0; ch < 9; ++ch) {
        for (int i = tid; i < 96 * 32; i += NT) {           // stage split weights
            int c = i >> 5, j = i & 31;
            float wv = g_wqkvT[c * 288 + ch * 32 + j];
            unsigned hi, lo; split2(wv, hi, lo);
            wh[c * SW_LD + j] = __uint_as_float(hi);
            wl[c * SW_LD + j] = __uint_as_float(lo);
        }
        __syncthreads();

        for (int job = warp; job < 28; job += 16) {          // 7 m-tiles x 4 n8-tiles
            int m0 = (job >> 2) * 16;
            int jloc = (job & 3) * 8;
            float4 d = make_float4(0.f, 0.f, 0.f, 0.f);
            const float* ab = sx + (m0 + gid) * SX_LD + tig;
            #pragma unroll 4
            for (int c0 = 0; c0 < 96; c0 += 8) {
                unsigned ah[4], al[4];
                split2(ab[c0],                 ah[0], al[0]);
                split2(ab[8 * SX_LD + c0],     ah[1], al[1]);
                split2(ab[c0 + 4],             ah[2], al[2]);
                split2(ab[8 * SX_LD + c0 + 4], ah[3], al[3]);
                const float* wph = wh + (c0 + tig) * SW_LD + jloc + gid;
                const float* wpl = wl + (c0 + tig) * SW_LD + jloc + gid;
                unsigned bh0 = __float_as_uint(wph[0]);
                unsigned bh1 = __float_as_uint(wph[4 * SW_LD]);
                unsigned bl0 = __float_as_uint(wpl[0]);
                unsigned bl1 = __float_as_uint(wpl[4 * SW_LD]);
                mma8(d, ah, bh0, bh1);
                mma8(d, al, bh0, bh1);
                mma8(d, ah, bl0, bl1);
            }
            int j = ch * 32 + jloc + 2 * tig;
            float2 bb = *(const float2*)(qkv_b + j);
            int r0 = m0 + gid, r1 = r0 + 8;
            float v00 = d.x + bb.x, v01 = d.y + bb.y;
            float v10 = d.z + bb.x, v11 = d.w + bb.y;
            if (j < 96) {                                    // q: fp32
                if (r0 < 98) *(float2*)(sq + r0 * SQ_LD + j) = make_float2(v00, v01);
                if (r1 < 98) *(float2*)(sq + r1 * SQ_LD + j) = make_float2(v10, v11);
            } else if (j < 192) {                            // k: transpose + tf32-round
                int jj = j - 96;
                if (r0 < 98) {
                    kt[jj * KT_LD + r0]       = __uint_as_float(t32(v00));
                    kt[(jj + 1) * KT_LD + r0] = __uint_as_float(t32(v01));
                }
                if (r1 < 98) {
                    kt[jj * KT_LD + r1]       = __uint_as_float(t32(v10));
                    kt[(jj + 1) * KT_LD + r1] = __uint_as_float(t32(v11));
                }
            } else {                                         // v: tf32-round
                int jj = j - 192;
                if (r0 < 98) *(float2*)(sv + r0 * SV_LD + jj) =
                    make_float2(__uint_as_float(t32(v00)), __uint_as_float(t32(v01)));
                if (r1 < 98) *(float2*)(sv + r1 * SV_LD + jj) =
                    make_float2(__uint_as_float(t32(v10)), __uint_as_float(t32(v11)));
            }
        }
        __syncthreads();
    }

    // re-zero sa pad cols 98..107 for rows 0..97 (w staging polluted the sa region)
    for (int i = tid; i < 98 * 10; i += NT) {
        int r = i / 10, c = 98 + (i - r * 10);
        sa[r * SA_LD + c] = 0.f;
    }
    // (sync before first PV read is provided by the post-scores/softmax syncs)

    // ============ attention per head ============
    for (int h = 0; h < 3; ++h) {
        // ---- scores: Q split-on-fly x K(tf32) ----
        for (int job = warp; job < 28; job += 16) {          // 7 m-tiles x 4 col-groups
            int m0 = (job >> 2) * 16;
            int g4 = job & 3;
            int nt0 = g4 * 4;
            int ntn = (g4 < 3) ? 4 : 1;                      // 13 n8-tiles total
            float4 d[4];
            #pragma unroll
            for (int t = 0; t < 4; ++t) d[t] = make_float4(0.f, 0.f, 0.f, 0.f);
            const float* qb = sq + (m0 + gid) * SQ_LD + h * 32 + tig;
            #pragma unroll
            for (int c0 = 0; c0 < 32; c0 += 8) {
                unsigned ah[4], al[4];
                split2(qb[c0],                 ah[0], al[0]);
                split2(qb[8 * SQ_LD + c0],     ah[1], al[1]);
                split2(qb[c0 + 4],             ah[2], al[2]);
                split2(qb[8 * SQ_LD + c0 + 4], ah[3], al[3]);
                const float* kb = kt + (h * 32 + c0 + tig) * KT_LD + gid;
                #pragma unroll
                for (int t = 0; t < 4; ++t) {
                    if (t < ntn) {
                        unsigned b0 = __float_as_uint(kb[(nt0 + t) * 8]);
                        unsigned b1 = __float_as_uint(kb[4 * KT_LD + (nt0 + t) * 8]);
                        mma8(d[t], ah, b0, b1);
                        mma8(d[t], al, b0, b1);
                    }
                }
            }
            int r0 = m0 + gid, r1 = r0 + 8;
            #pragma unroll
            for (int t = 0; t < 4; ++t) {
                if (t < ntn) {
                    int mc = (nt0 + t) * 8 + 2 * tig;
                    if (mc < 98) {                            // pairs (mc,mc+1), mc even
                        const float* gbp = g_bias + h * 9800 + mc;
                        if (r0 < 98) {
                            float2 bv = *(const float2*)(gbp + r0 * 100);
                            *(float2*)(sa + r0 * SA_LD + mc) =
                                make_float2(d[t].x * SCALEF + bv.x, d[t].y * SCALEF + bv.y);
                        }
                        if (r1 < 98) {
                            float2 bv = *(const float2*)(gbp + r1 * 100);
                            *(float2*)(sa + r1 * SA_LD + mc) =
                                make_float2(d[t].z * SCALEF + bv.x, d[t].w * SCALEF + bv.y);
                        }
                    }
                }
            }
        }
        __syncthreads();

        // ---- softmax (warp per row; N=98 = 3*32+2) ----
        for (int r = warp; r < 98; r += 16) {
            float* row = sa + r * SA_LD;
            float v0 = row[lane];
            float va = row[lane + 32];
            float vb = row[lane + 64];
            bool  g3 = (lane < 2);
            float vc = g3 ? row[lane + 96] : -1e30f;
            float mx = fmaxf(fmaxf(v0, va), fmaxf(vb, vc));
            #pragma unroll
            for (int s = 16; s; s >>= 1) mx = fmaxf(mx, __shfl_xor_sync(~0u, mx, s));
            float e0 = __expf(v0 - mx);
            float e1 = __expf(va - mx);
            float e2 = __expf(vb - mx);
            float e3 = g3 ? __expf(vc - mx) : 0.f;
            row[lane] = e0; row[lane + 32] = e1; row[lane + 64] = e2;
            if (g3) row[lane + 96] = e3;
            float s = e0 + e1 + e2 + e3;
            #pragma unroll
            for (int sh = 16; sh; sh >>= 1) s += __shfl_xor_sync(~0u, s, sh);
            if (lane == 0) ri[r] = 1.0f / s;
        }
        __syncthreads();

        // ---- PV: P split-on-fly x V(tf32); 14 jobs of m16 x n16 ----
        if (warp < 14) {
            int m0 = (warp >> 1) * 16;
            int half = warp & 1;
            float4 d[2];
            d[0] = make_float4(0.f, 0.f, 0.f, 0.f); d[1] = d[0];
            const float* pb = sa + (m0 + gid) * SA_LD + tig;
            const float* vb = sv + tig * SV_LD + h * 32 + half * 16 + gid;
            #pragma unroll 2
            for (int c0 = 0; c0 < 104; c0 += 8) {            // 13 k-steps (pad cols zero)
                unsigned ah[4], al[4];
                split2(pb[c0],                 ah[0], al[0]);
                split2(pb[8 * SA_LD + c0],     ah[1], al[1]);
                split2(pb[c0 + 4],             ah[2], al[2]);
                split2(pb[8 * SA_LD + c0 + 4], ah[3], al[3]);
                const float* vp = vb + c0 * SV_LD;
                #pragma unroll
                for (int t = 0; t < 2; ++t) {
                    unsigned b0 = __float_as_uint(vp[t * 8]);
                    unsigned b1 = __float_as_uint(vp[4 * SV_LD + t * 8]);
                    mma8(d[t], ah, b0, b1);
                    mma8(d[t], al, b0, b1);
                }
            }
            int r0 = m0 + gid, r1 = r0 + 8;
            int col = h * 32 + half * 16 + 2 * tig;
            if (r0 < 98) {
                float rv = ri[r0];
                *(float2*)(sx + r0 * SX_LD + col)     = make_float2(d[0].x * rv, d[0].y * rv);
                *(float2*)(sx + r0 * SX_LD + col + 8) = make_float2(d[1].x * rv, d[1].y * rv);
            }
            if (r1 < 98) {
                float rv = ri[r1];
                *(float2*)(sx + r1 * SX_LD + col)     = make_float2(d[0].z * rv, d[0].w * rv);
                *(float2*)(sx + r1 * SX_LD + col + 8) = make_float2(d[1].z * rv, d[1].w * rv);
            }
        }
        __syncthreads();
    }

    // ============ proj: out = attn_out @ proj_w^T + b  (3 chunks of 32) ============
    float* ob = out + (size_t)b * 9408;
    for (int ch = 0; ch < 3; ++ch) {
        for (int i = tid; i < 96 * 32; i += NT) {
            int c = i >> 5, j = i & 31;
            float wv = g_wprojT[c * 96 + ch * 32 + j];
            unsigned hi, lo; split2(wv, hi, lo);
            wh[c * SW_LD + j] = __uint_as_float(hi);
            wl[c * SW_LD + j] = __uint_as_float(lo);
        }
        __syncthreads();

        for (int job = warp; job < 28; job += 16) {
            int m0 = (job >> 2) * 16;
            int jloc = (job & 3) * 8;
            float4 d = make_float4(0.f, 0.f, 0.f, 0.f);
            const float* ab = sx + (m0 + gid) * SX_LD + tig;
            #pragma unroll 4
            for (int c0 = 0; c0 < 96; c0 += 8) {
                unsigned ah[4], al[4];
                split2(ab[c0],                 ah[0], al[0]);
                split2(ab[8 * SX_LD + c0],     ah[1], al[1]);
                split2(ab[c0 + 4],             ah[2], al[2]);
                split2(ab[8 * SX_LD + c0 + 4], ah[3], al[3]);
                const float* wph = wh + (c0 + tig) * SW_LD + jloc + gid;
                const float* wpl = wl + (c0 + tig) * SW_LD + jloc + gid;
                unsigned bh0 = __float_as_uint(wph[0]);
                unsigned bh1 = __float_as_uint(wph[4 * SW_LD]);
                unsigned bl0 = __float_as_uint(wpl[0]);
                unsigned bl1 = __float_as_uint(wpl[4 * SW_LD]);
                mma8(d, ah, bh0, bh1);
                mma8(d, al, bh0, bh1);
                mma8(d, ah, bl0, bl1);
            }
            int j = ch * 32 + jloc + 2 * tig;
            float2 bb = *(const float2*)(proj_b + j);
            int r0 = m0 + gid, r1 = r0 + 8;
            if (r0 < 98) *(float2*)(ob + r0 * 96 + j) = make_float2(d.x + bb.x, d.y + bb.y);
            if (r1 < 98) *(float2*)(ob + r1 * 96 + j) = make_float2(d.z + bb.x, d.w + bb.y);
        }
        __syncthreads();
    }
}

extern "C" void kernel_launch(void* const* d_in, const int* in_sizes, int n_in,
                              void* d_out, int out_size)
{
    const float* x          = (const float*)d_in[0];
    const float* qkv_w      = (const float*)d_in[1];
    const float* qkv_b      = (const float*)d_in[2];
    const float* proj_w     = (const float*)d_in[3];
    const float* proj_b     = (const float*)d_in[4];
    const float* bias_table = (const float*)d_in[5];
    const int*   rel_index  = (const int*)d_in[6];
    float* out = (float*)d_out;

    int prep_total = 96 * 288 + 96 * 96 + 3 * 98 * 100;
    prep_kernel<<<(prep_total + 255) / 256, 256>>>(qkv_w, proj_w, bias_table, rel_index);

    cudaFuncSetAttribute(wa3d_main, cudaFuncAttributeMaxDynamicSharedMemorySize, SMEM_BYTES);
    wa3d_main<<<4096, NT, SMEM_BYTES>>>(x, qkv_b, proj_b, out);
}

// round 9
// speedup vs baseline: 1.6757x; 1.6757x over previous
#include <cuda_runtime.h>

#define NT 512
#define SCALEF 0.17677669529663687f   // 1/sqrt(32)

// smem strides (floats) — all chosen conflict-free for the MMA frag patterns
#define SX_LD 100   // A-pattern: 100%32=4 -> gid*4+tig distinct
#define SQ_LD 100
#define SK_LD 100   // scores B-pattern same as A-pattern (K stored [m][d])
#define SV_LD 104   // PV B-pattern: 104%32=8 -> tig*8+gid distinct
#define SA_LD 108   // PV A-pattern: 108%32=12 -> gid*12+tig distinct

// region offsets (floats)
#define OFF_SX  0        // [98][100] = 9800 (A-overflow reads land in sq: allocated)
#define OFF_SQ  9800     // [98][100]
#define OFF_SK  19600    // [104][100] = 10400 (rows 98..103 zeroed)
#define OFF_SV  30000    // [104][104] = 10816 (rows 98..103 zeroed)
#define OFF_SAW 40816    // union: sa [98][108] (pads zeroed) / weight stage 12288
#define OFF_RI  53104    // 112
#define SMEM_FLOATS 53216
#define SMEM_BYTES (SMEM_FLOATS * 4)   // 212,864 B

__device__ float g_w1[9 * 6144];       // GEMM1 weights: frag-permuted, hi/lo interleaved
__device__ float g_wp[3 * 6144];       // proj weights: same layout
__device__ float g_bias[3 * 98 * 100]; // bias[h][n][m], m padded to 100 (pad=0)

__device__ __forceinline__ unsigned t32(float f) {
    unsigned u; asm("cvt.rna.tf32.f32 %0, %1;" : "=r"(u) : "f"(f)); return u;
}
__device__ __forceinline__ void mma8(float& d0, float& d1, float& d2, float& d3,
                                     unsigned a0, unsigned a1, unsigned a2, unsigned a3,
                                     unsigned b0, unsigned b1) {
    asm volatile(
        "mma.sync.aligned.m16n8k8.row.col.f32.tf32.tf32.f32 "
        "{%0,%1,%2,%3},{%4,%5,%6,%7},{%8,%9},{%0,%1,%2,%3};"
        : "+f"(d0), "+f"(d1), "+f"(d2), "+f"(d3)
        : "r"(a0), "r"(a1), "r"(a2), "r"(a3), "r"(b0), "r"(b1));
}

// ---- prep: frag-permuted pre-split weights + padded bias ----
// layout: quad q -> lane = q&31, tk = q>>5; ch = tk/48; ks = (tk%48)>>2; t = tk&3
// b0 = W[(ch*32 + t*8 + gid)*96 + ks*8 + tig], b1 = +4 in k; store {hi0,hi1,lo0,lo1}
__global__ void prep_kernel(const float* __restrict__ qkv_w,
                            const float* __restrict__ proj_w,
                            const float* __restrict__ table,
                            const int* __restrict__ rel)
{
    int i = blockIdx.x * blockDim.x + threadIdx.x;
    if (i < 13824) {
        int lane = i & 31, tk = i >> 5;
        int ch = tk / 48, rem = tk - ch * 48;
        int ks = rem >> 2, t = rem & 3;
        int gid = lane >> 2, tig = lane & 3;
        int col = ch * 32 + t * 8 + gid, c = ks * 8 + tig;
        float w0 = qkv_w[col * 96 + c], w1 = qkv_w[col * 96 + c + 4];
        float4 v;
        v.x = __uint_as_float(t32(w0)); v.y = __uint_as_float(t32(w1));
        v.z = __uint_as_float(t32(w0 - v.x)); v.w = __uint_as_float(t32(w1 - v.y));
        ((float4*)g_w1)[i] = v;
    } else if (i < 18432) {
        int q = i - 13824;
        int lane = q & 31, tk = q >> 5;
        int ch = tk / 48, rem = tk - ch * 48;
        int ks = rem >> 2, t = rem & 3;
        int gid = lane >> 2, tig = lane & 3;
        int col = ch * 32 + t * 8 + gid, c = ks * 8 + tig;
        float w0 = proj_w[col * 96 + c], w1 = proj_w[col * 96 + c + 4];
        float4 v;
        v.x = __uint_as_float(t32(w0)); v.y = __uint_as_float(t32(w1));
        v.z = __uint_as_float(t32(w0 - v.x)); v.w = __uint_as_float(t32(w1 - v.y));
        ((float4*)g_wp)[q] = v;
    } else if (i < 18432 + 29400) {
        int k = i - 18432;
        int h = k / 9800, r = k - h * 9800;
        int n = r / 100, m = r - n * 100;
        g_bias[k] = (m < 98) ? table[rel[n * 98 + m] * 3 + h] : 0.f;
    }
}

__global__ void __launch_bounds__(NT, 1)
wa3d_main(const float* __restrict__ x, const float* __restrict__ qkv_b,
          const float* __restrict__ proj_b, float* __restrict__ out)
{
    extern __shared__ float sm[];
    float* sx  = sm + OFF_SX;    // x, later attention output
    float* sq  = sm + OFF_SQ;    // q fp32 [m][96]
    float* sk  = sm + OFF_SK;    // k tf32-bits [m][96] (row-major: IS the scores B-frag)
    float* sv  = sm + OFF_SV;    // v tf32-bits [m][96]
    float* sa  = sm + OFF_SAW;   // scores/probs (union with weight stage)
    float* smW = sm + OFF_SAW;   // weight stage buffer
    float* ri  = sm + OFF_RI;

    const int b    = blockIdx.x;
    const int tid  = threadIdx.x;
    const int warp = tid >> 5, lane = tid & 31;
    const int gid  = lane >> 2;   // 0..7
    const int tig  = lane & 3;    // 0..3

    float4 pf[6];

    // ---- prefetch weight stage 0 (latency overlapped with staging below) ----
    {
        const float4* src = (const float4*)g_w1;
        #pragma unroll
        for (int j = 0; j < 6; ++j) pf[j] = src[tid + j * 512];
    }
    // ---- zero pad strips (k/v rows 98..103) ----
    for (int i = tid; i < 600; i += NT) sk[9800 + i] = 0.f;
    for (int i = tid; i < 624; i += NT) sv[10192 + i] = 0.f;
    // ---- stage x[b] ----
    const float* xb = x + (size_t)b * 9408;
    for (int i = tid; i < 9408; i += NT) {
        int r = i / 96, c = i - r * 96;
        sx[r * SX_LD + c] = xb[i];
    }
    // ---- store weight stage 0 ----
    {
        float4* dst = (float4*)smW;
        #pragma unroll
        for (int j = 0; j < 6; ++j) dst[tid + j * 512] = pf[j];
    }
    __syncthreads();

    // ============ GEMM1: qkv = x @ qkv_w^T + b; 5 stages of 64(32) cols ============
    for (int s = 0; s < 5; ++s) {
        if (s < 4) {                     // prefetch next stage
            int nf = (s == 3) ? 3 : 6;
            const float4* src = (const float4*)(g_w1 + (s + 1) * 12288);
            #pragma unroll
            for (int j = 0; j < 6; ++j) if (j < nf) pf[j] = src[tid + j * 512];
        }
        int njobs = (s < 4) ? 14 : 7;
        if (warp < njobs) {
            int mt = warp % 7, chL = warp / 7;
            int chID = 2 * s + chL;
            const float* ap = sx + (mt * 16 + gid) * SX_LD + tig;
            const float* wp = smW + chL * 6144 + lane * 4;
            float d[4][4];
            #pragma unroll
            for (int t = 0; t < 4; ++t) { d[t][0] = d[t][1] = d[t][2] = d[t][3] = 0.f; }
            #pragma unroll
            for (int ks = 0; ks < 12; ++ks) {
                unsigned a0 = t32(ap[ks * 8]);
                unsigned a1 = t32(ap[8 * SX_LD + ks * 8]);
                unsigned a2 = t32(ap[ks * 8 + 4]);
                unsigned a3 = t32(ap[8 * SX_LD + ks * 8 + 4]);
                #pragma unroll
                for (int t = 0; t < 4; ++t) {
                    float4 w4 = *(const float4*)(wp + ks * 512 + t * 128);
                    mma8(d[t][0], d[t][1], d[t][2], d[t][3], a0, a1, a2, a3,
                         __float_as_uint(w4.x), __float_as_uint(w4.y));
                    mma8(d[t][0], d[t][1], d[t][2], d[t][3], a0, a1, a2, a3,
                         __float_as_uint(w4.z), __float_as_uint(w4.w));
                }
            }
            int r0 = mt * 16 + gid, r1 = r0 + 8;
            int j0 = chID * 32;
            #pragma unroll
            for (int t = 0; t < 4; ++t) {
                int j = j0 + t * 8 + 2 * tig;
                float2 bb = *(const float2*)(qkv_b + j);
                float v00 = d[t][0] + bb.x, v01 = d[t][1] + bb.y;
                float v10 = d[t][2] + bb.x, v11 = d[t][3] + bb.y;
                if (chID < 3) {                                   // q: fp32
                    if (r0 < 98) *(float2*)(sq + r0 * SQ_LD + j) = make_float2(v00, v01);
                    if (r1 < 98) *(float2*)(sq + r1 * SQ_LD + j) = make_float2(v10, v11);
                } else if (chID < 6) {                            // k: tf32 bits
                    int jj = j - 96;
                    if (r0 < 98) *(float2*)(sk + r0 * SK_LD + jj) =
                        make_float2(__uint_as_float(t32(v00)), __uint_as_float(t32(v01)));
                    if (r1 < 98) *(float2*)(sk + r1 * SK_LD + jj) =
                        make_float2(__uint_as_float(t32(v10)), __uint_as_float(t32(v11)));
                } else {                                          // v: tf32 bits
                    int jj = j - 192;
                    if (r0 < 98) *(float2*)(sv + r0 * SV_LD + jj) =
                        make_float2(__uint_as_float(t32(v00)), __uint_as_float(t32(v01)));
                    if (r1 < 98) *(float2*)(sv + r1 * SV_LD + jj) =
                        make_float2(__uint_as_float(t32(v10)), __uint_as_float(t32(v11)));
                }
            }
        }
        __syncthreads();
        if (s < 4) {
            int nf = (s == 3) ? 3 : 6;
            float4* dst = (float4*)smW;
            #pragma unroll
            for (int j = 0; j < 6; ++j) if (j < nf) dst[tid + j * 512] = pf[j];
            __syncthreads();
        }
    }

    // ============ attention per head ============
    for (int h = 0; h < 3; ++h) {
        if (h == 0) {     // zero sa pad cols 98..103 (W-stage polluted the union)
            for (int i = tid; i < 98 * 6; i += NT) {
                int r = i / 6, c = 98 + (i - r * 6);
                sa[r * SA_LD + c] = 0.f;
            }
        }
        // ---- scores: Q(split) x K(tf32, row-major = B-frag) ----
        for (int job = warp; job < 28; job += 16) {
            int mt = job >> 2, g4 = job & 3;
            int ntn = (g4 < 3) ? 4 : 1;
            const float* qb = sq + (mt * 16 + gid) * SQ_LD + h * 32 + tig;
            const float* kb = sk + gid * SK_LD + h * 32 + tig;
            float d[4][4];
            #pragma unroll
            for (int t = 0; t < 4; ++t) { d[t][0] = d[t][1] = d[t][2] = d[t][3] = 0.f; }
            #pragma unroll
            for (int c0 = 0; c0 < 32; c0 += 8) {
                float f0 = qb[c0], f1 = qb[8 * SQ_LD + c0];
                float f2 = qb[c0 + 4], f3 = qb[8 * SQ_LD + c0 + 4];
                unsigned h0 = t32(f0), h1 = t32(f1), h2 = t32(f2), h3 = t32(f3);
                unsigned l0 = t32(f0 - __uint_as_float(h0));
                unsigned l1 = t32(f1 - __uint_as_float(h1));
                unsigned l2 = t32(f2 - __uint_as_float(h2));
                unsigned l3 = t32(f3 - __uint_as_float(h3));
                #pragma unroll
                for (int t = 0; t < 4; ++t) {
                    if (t < ntn) {
                        const float* kp = kb + ((g4 * 4 + t) * 8) * SK_LD + c0;
                        unsigned b0 = __float_as_uint(kp[0]);
                        unsigned b1 = __float_as_uint(kp[4]);
                        mma8(d[t][0], d[t][1], d[t][2], d[t][3], h0, h1, h2, h3, b0, b1);
                        mma8(d[t][0], d[t][1], d[t][2], d[t][3], l0, l1, l2, l3, b0, b1);
                    }
                }
            }
            int r0 = mt * 16 + gid, r1 = r0 + 8;
            #pragma unroll
            for (int t = 0; t < 4; ++t) {
                if (t < ntn) {
                    int mc = (g4 * 4 + t) * 8 + 2 * tig;
                    if (mc < 98) {
                        const float* gbp = g_bias + h * 9800 + mc;
                        if (r0 < 98) {
                            float2 bv = *(const float2*)(gbp + r0 * 100);
                            *(float2*)(sa + r0 * SA_LD + mc) =
                                make_float2(d[t][0] * SCALEF + bv.x, d[t][1] * SCALEF + bv.y);
                        }
                        if (r1 < 98) {
                            float2 bv = *(const float2*)(gbp + r1 * 100);
                            *(float2*)(sa + r1 * SA_LD + mc) =
                                make_float2(d[t][2] * SCALEF + bv.x, d[t][3] * SCALEF + bv.y);
                        }
                    }
                }
            }
        }
        __syncthreads();

        // ---- softmax (warp per row; N=98 = 3*32+2) ----
        for (int r = warp; r < 98; r += 16) {
            float* row = sa + r * SA_LD;
            float v0 = row[lane];
            float va = row[lane + 32];
            float vb = row[lane + 64];
            bool  g3 = (lane < 2);
            float vc = g3 ? row[lane + 96] : -1e30f;
            float mx = fmaxf(fmaxf(v0, va), fmaxf(vb, vc));
            #pragma unroll
            for (int s2 = 16; s2; s2 >>= 1) mx = fmaxf(mx, __shfl_xor_sync(~0u, mx, s2));
            float e0 = __expf(v0 - mx);
            float e1 = __expf(va - mx);
            float e2 = __expf(vb - mx);
            float e3 = g3 ? __expf(vc - mx) : 0.f;
            row[lane] = e0; row[lane + 32] = e1; row[lane + 64] = e2;
            if (g3) row[lane + 96] = e3;
            float s2s = e0 + e1 + e2 + e3;
            #pragma unroll
            for (int sh = 16; sh; sh >>= 1) s2s += __shfl_xor_sync(~0u, s2s, sh);
            if (lane == 0) ri[r] = 1.0f / s2s;
        }
        __syncthreads();

        // ---- PV: P(split) x V(tf32) ; 14 jobs m16 x n16 ----
        if (warp < 14) {
            int mt = warp >> 1, hf = warp & 1;
            const float* pb = sa + (mt * 16 + gid) * SA_LD + tig;
            const float* vp0 = sv + tig * SV_LD + h * 32 + hf * 16 + gid;
            float d[2][4];
            d[0][0] = d[0][1] = d[0][2] = d[0][3] = 0.f;
            d[1][0] = d[1][1] = d[1][2] = d[1][3] = 0.f;
            #pragma unroll
            for (int c0 = 0; c0 < 104; c0 += 8) {
                float f0 = pb[c0], f1 = pb[8 * SA_LD + c0];
                float f2 = pb[c0 + 4], f3 = pb[8 * SA_LD + c0 + 4];
                unsigned h0 = t32(f0), h1 = t32(f1), h2 = t32(f2), h3 = t32(f3);
                unsigned l0 = t32(f0 - __uint_as_float(h0));
                unsigned l1 = t32(f1 - __uint_as_float(h1));
                unsigned l2 = t32(f2 - __uint_as_float(h2));
                unsigned l3 = t32(f3 - __uint_as_float(h3));
                #pragma unroll
                for (int t = 0; t < 2; ++t) {
                    const float* vp = vp0 + c0 * SV_LD + t * 8;
                    unsigned b0 = __float_as_uint(vp[0]);
                    unsigned b1 = __float_as_uint(vp[4 * SV_LD]);
                    mma8(d[t][0], d[t][1], d[t][2], d[t][3], h0, h1, h2, h3, b0, b1);
                    mma8(d[t][0], d[t][1], d[t][2], d[t][3], l0, l1, l2, l3, b0, b1);
                }
            }
            int r0 = mt * 16 + gid, r1 = r0 + 8;
            int col = h * 32 + hf * 16 + 2 * tig;
            if (r0 < 98) {
                float rv = ri[r0];
                *(float2*)(sx + r0 * SX_LD + col)     = make_float2(d[0][0] * rv, d[0][1] * rv);
                *(float2*)(sx + r0 * SX_LD + col + 8) = make_float2(d[1][0] * rv, d[1][1] * rv);
            }
            if (r1 < 98) {
                float rv = ri[r1];
                *(float2*)(sx + r1 * SX_LD + col)     = make_float2(d[0][2] * rv, d[0][3] * rv);
                *(float2*)(sx + r1 * SX_LD + col + 8) = make_float2(d[1][2] * rv, d[1][3] * rv);
            }
        }
        __syncthreads();
    }

    // ============ proj: out = attn_out @ proj_w^T + b; 2 stages ============
    float* ob = out + (size_t)b * 9408;
    {
        const float4* src = (const float4*)g_wp;
        #pragma unroll
        for (int j = 0; j < 6; ++j) pf[j] = src[tid + j * 512];
        float4* dst = (float4*)smW;
        #pragma unroll
        for (int j = 0; j < 6; ++j) dst[tid + j * 512] = pf[j];
    }
    __syncthreads();
    for (int s = 0; s < 2; ++s) {
        if (s == 0) {   // prefetch stage 1 (chunk 2)
            const float4* src = (const float4*)(g_wp + 12288);
            #pragma unroll
            for (int j = 0; j < 3; ++j) pf[j] = src[tid + j * 512];
        }
        int njobs = (s == 0) ? 14 : 7;
        if (warp < njobs) {
            int mt = warp % 7, chL = warp / 7;
            int chID = 2 * s + chL;
            const float* ap = sx + (mt * 16 + gid) * SX_LD + tig;
            const float* wp = smW + chL * 6144 + lane * 4;
            float d[4][4];
            #pragma unroll
            for (int t = 0; t < 4; ++t) { d[t][0] = d[t][1] = d[t][2] = d[t][3] = 0.f; }
            #pragma unroll
            for (int ks = 0; ks < 12; ++ks) {
                unsigned a0 = t32(ap[ks * 8]);
                unsigned a1 = t32(ap[8 * SX_LD + ks * 8]);
                unsigned a2 = t32(ap[ks * 8 + 4]);
                unsigned a3 = t32(ap[8 * SX_LD + ks * 8 + 4]);
                #pragma unroll
                for (int t = 0; t < 4; ++t) {
                    float4 w4 = *(const float4*)(wp + ks * 512 + t * 128);
                    mma8(d[t][0], d[t][1], d[t][2], d[t][3], a0, a1, a2, a3,
                         __float_as_uint(w4.x), __float_as_uint(w4.y));
                    mma8(d[t][0], d[t][1], d[t][2], d[t][3], a0, a1, a2, a3,
                         __float_as_uint(w4.z), __float_as_uint(w4.w));
                }
            }
            int r0 = mt * 16 + gid, r1 = r0 + 8;
            int j0 = chID * 32;
            #pragma unroll
            for (int t = 0; t < 4; ++t) {
                int j = j0 + t * 8 + 2 * tig;
                float2 bb = *(const float2*)(proj_b + j);
                if (r0 < 98) *(float2*)(ob + r0 * 96 + j) =
                    make_float2(d[t][0] + bb.x, d[t][1] + bb.y);
                if (r1 < 98) *(float2*)(ob + r1 * 96 + j) =
                    make_float2(d[t][2] + bb.x, d[t][3] + bb.y);
            }
        }
        __syncthreads();
        if (s == 0) {
            float4* dst = (float4*)smW;
            #pragma unroll
            for (int j = 0; j < 3; ++j) dst[tid + j * 512] = pf[j];
            __syncthreads();
        }
    }
}

extern "C" void kernel_launch(void* const* d_in, const int* in_sizes, int n_in,
                              void* d_out, int out_size)
{
    const float* x          = (const float*)d_in[0];
    const float* qkv_w      = (const float*)d_in[1];
    const float* qkv_b      = (const float*)d_in[2];
    const float* proj_w     = (const float*)d_in[3];
    const float* proj_b     = (const float*)d_in[4];
    const float* bias_table = (const float*)d_in[5];
    const int*   rel_index  = (const int*)d_in[6];
    float* out = (float*)d_out;

    int prep_total = 18432 + 29400;
    prep_kernel<<<(prep_total + 255) / 256, 256>>>(qkv_w, proj_w, bias_table, rel_index);

    cudaFuncSetAttribute(wa3d_main, cudaFuncAttributeMaxDynamicSharedMemorySize, SMEM_BYTES);
    wa3d_main<<<4096, NT, SMEM_BYTES>>>(x, qkv_b, proj_b, out);
}

// round 10
// speedup vs baseline: 1.7778x; 1.0609x over previous
#include <cuda_runtime.h>

#define NT 512
#define SCALEF 0.17677669529663687f   // 1/sqrt(32)

// smem strides (floats) — all chosen conflict-free for the MMA frag patterns
#define SX_LD 100   // A-pattern: 100%32=4 -> gid*4+tig distinct
#define SQ_LD 100
#define SK_LD 100   // scores B-pattern same as A-pattern (K stored [m][d])
#define SV_LD 104   // PV B-pattern: 104%32=8 -> tig*8+gid distinct
#define SA_LD 108   // PV A-pattern: 108%32=12 -> gid*12+tig distinct

// region offsets (floats)
#define OFF_SX  0        // [98][100] = 9800 (A-overflow reads land in sq: allocated)
#define OFF_SQ  9800     // [98][100]
#define OFF_SK  19600    // [104][100] = 10400 (rows 98..103 zeroed)
#define OFF_SV  30000    // [104][104] = 10816 (rows 98..103 zeroed)
#define OFF_SAW 40816    // union: sa [98][108] (pads zeroed) / weight stage 12288
#define OFF_RI  53104    // 112
#define SMEM_FLOATS 53216
#define SMEM_BYTES (SMEM_FLOATS * 4)   // 212,864 B

__device__ float g_w1[9 * 6144];       // GEMM1 weights: frag-permuted, hi/lo interleaved
__device__ float g_wp[3 * 6144];       // proj weights: same layout
__device__ float g_bias[3 * 98 * 100]; // bias[h][n][m], m padded to 100 (pad=0)

__device__ __forceinline__ unsigned t32(float f) {
    unsigned u; asm("cvt.rna.tf32.f32 %0, %1;" : "=r"(u) : "f"(f)); return u;
}
__device__ __forceinline__ void mma8(float& d0, float& d1, float& d2, float& d3,
                                     unsigned a0, unsigned a1, unsigned a2, unsigned a3,
                                     unsigned b0, unsigned b1) {
    asm volatile(
        "mma.sync.aligned.m16n8k8.row.col.f32.tf32.tf32.f32 "
        "{%0,%1,%2,%3},{%4,%5,%6,%7},{%8,%9},{%0,%1,%2,%3};"
        : "+f"(d0), "+f"(d1), "+f"(d2), "+f"(d3)
        : "r"(a0), "r"(a1), "r"(a2), "r"(a3), "r"(b0), "r"(b1));
}

// ---- prep: frag-permuted pre-split weights + padded bias ----
__global__ void prep_kernel(const float* __restrict__ qkv_w,
                            const float* __restrict__ proj_w,
                            const float* __restrict__ table,
                            const int* __restrict__ rel)
{
    int i = blockIdx.x * blockDim.x + threadIdx.x;
    if (i < 13824) {
        int lane = i & 31, tk = i >> 5;
        int ch = tk / 48, rem = tk - ch * 48;
        int ks = rem >> 2, t = rem & 3;
        int gid = lane >> 2, tig = lane & 3;
        int col = ch * 32 + t * 8 + gid, c = ks * 8 + tig;
        float w0 = qkv_w[col * 96 + c], w1 = qkv_w[col * 96 + c + 4];
        float4 v;
        v.x = __uint_as_float(t32(w0)); v.y = __uint_as_float(t32(w1));
        v.z = __uint_as_float(t32(w0 - v.x)); v.w = __uint_as_float(t32(w1 - v.y));
        ((float4*)g_w1)[i] = v;
    } else if (i < 18432) {
        int q = i - 13824;
        int lane = q & 31, tk = q >> 5;
        int ch = tk / 48, rem = tk - ch * 48;
        int ks = rem >> 2, t = rem & 3;
        int gid = lane >> 2, tig = lane & 3;
        int col = ch * 32 + t * 8 + gid, c = ks * 8 + tig;
        float w0 = proj_w[col * 96 + c], w1 = proj_w[col * 96 + c + 4];
        float4 v;
        v.x = __uint_as_float(t32(w0)); v.y = __uint_as_float(t32(w1));
        v.z = __uint_as_float(t32(w0 - v.x)); v.w = __uint_as_float(t32(w1 - v.y));
        ((float4*)g_wp)[q] = v;
    } else if (i < 18432 + 29400) {
        int k = i - 18432;
        int h = k / 9800, r = k - h * 9800;
        int n = r / 100, m = r - n * 100;
        g_bias[k] = (m < 98) ? table[rel[n * 98 + m] * 3 + h] : 0.f;
    }
}

__global__ void __launch_bounds__(NT, 1)
wa3d_main(const float* __restrict__ x, const float* __restrict__ qkv_b,
          const float* __restrict__ proj_b, float* __restrict__ out)
{
    extern __shared__ float sm[];
    float* sx  = sm + OFF_SX;    // x, later attention output
    float* sq  = sm + OFF_SQ;    // q fp32 [m][96]
    float* sk  = sm + OFF_SK;    // k tf32-bits [m][96]
    float* sv  = sm + OFF_SV;    // v tf32-bits [m][96]
    float* sa  = sm + OFF_SAW;   // scores/probs (union with weight stage)
    float* smW = sm + OFF_SAW;   // weight stage buffer
    float* ri  = sm + OFF_RI;

    const int b    = blockIdx.x;
    const int tid  = threadIdx.x;
    const int warp = tid >> 5, lane = tid & 31;
    const int gid  = lane >> 2;   // 0..7
    const int tig  = lane & 3;    // 0..3

    float4 pf[6];

    // ---- prefetch weight stage 0 ----
    {
        const float4* src = (const float4*)g_w1;
        #pragma unroll
        for (int j = 0; j < 6; ++j) pf[j] = src[tid + j * 512];
    }
    // ---- zero pad strips (k/v rows 98..103) ----
    for (int i = tid; i < 600; i += NT) sk[9800 + i] = 0.f;
    for (int i = tid; i < 624; i += NT) sv[10192 + i] = 0.f;
    // ---- stage x[b] ----
    const float* xb = x + (size_t)b * 9408;
    for (int i = tid; i < 9408; i += NT) {
        int r = i / 96, c = i - r * 96;
        sx[r * SX_LD + c] = xb[i];
    }
    // ---- store weight stage 0 ----
    {
        float4* dst = (float4*)smW;
        #pragma unroll
        for (int j = 0; j < 6; ++j) dst[tid + j * 512] = pf[j];
    }
    __syncthreads();

    // ============ GEMM1: qkv = x @ qkv_w^T + b; 5 stages of 64(32) cols ============
    for (int s = 0; s < 5; ++s) {
        if (s < 4) {
            int nf = (s == 3) ? 3 : 6;
            const float4* src = (const float4*)(g_w1 + (s + 1) * 12288);
            #pragma unroll
            for (int j = 0; j < 6; ++j) if (j < nf) pf[j] = src[tid + j * 512];
        }
        int njobs = (s < 4) ? 14 : 7;
        if (warp < njobs) {
            int mt = warp % 7, chL = warp / 7;
            int chID = 2 * s + chL;
            const float* ap = sx + (mt * 16 + gid) * SX_LD + tig;
            const float* wp = smW + chL * 6144 + lane * 4;
            float d[4][4];
            #pragma unroll
            for (int t = 0; t < 4; ++t) { d[t][0] = d[t][1] = d[t][2] = d[t][3] = 0.f; }
            #pragma unroll
            for (int ks = 0; ks < 12; ++ks) {
                unsigned a0 = t32(ap[ks * 8]);
                unsigned a1 = t32(ap[8 * SX_LD + ks * 8]);
                unsigned a2 = t32(ap[ks * 8 + 4]);
                unsigned a3 = t32(ap[8 * SX_LD + ks * 8 + 4]);
                #pragma unroll
                for (int t = 0; t < 4; ++t) {
                    float4 w4 = *(const float4*)(wp + ks * 512 + t * 128);
                    mma8(d[t][0], d[t][1], d[t][2], d[t][3], a0, a1, a2, a3,
                         __float_as_uint(w4.x), __float_as_uint(w4.y));
                    mma8(d[t][0], d[t][1], d[t][2], d[t][3], a0, a1, a2, a3,
                         __float_as_uint(w4.z), __float_as_uint(w4.w));
                }
            }
            int r0 = mt * 16 + gid, r1 = r0 + 8;
            int j0 = chID * 32;
            #pragma unroll
            for (int t = 0; t < 4; ++t) {
                int j = j0 + t * 8 + 2 * tig;
                float2 bb = *(const float2*)(qkv_b + j);
                float v00 = d[t][0] + bb.x, v01 = d[t][1] + bb.y;
                float v10 = d[t][2] + bb.x, v11 = d[t][3] + bb.y;
                if (chID < 3) {
                    if (r0 < 98) *(float2*)(sq + r0 * SQ_LD + j) = make_float2(v00, v01);
                    if (r1 < 98) *(float2*)(sq + r1 * SQ_LD + j) = make_float2(v10, v11);
                } else if (chID < 6) {
                    int jj = j - 96;
                    if (r0 < 98) *(float2*)(sk + r0 * SK_LD + jj) =
                        make_float2(__uint_as_float(t32(v00)), __uint_as_float(t32(v01)));
                    if (r1 < 98) *(float2*)(sk + r1 * SK_LD + jj) =
                        make_float2(__uint_as_float(t32(v10)), __uint_as_float(t32(v11)));
                } else {
                    int jj = j - 192;
                    if (r0 < 98) *(float2*)(sv + r0 * SV_LD + jj) =
                        make_float2(__uint_as_float(t32(v00)), __uint_as_float(t32(v01)));
                    if (r1 < 98) *(float2*)(sv + r1 * SV_LD + jj) =
                        make_float2(__uint_as_float(t32(v10)), __uint_as_float(t32(v11)));
                }
            }
        }
        __syncthreads();
        if (s < 4) {
            int nf = (s == 3) ? 3 : 6;
            float4* dst = (float4*)smW;
            #pragma unroll
            for (int j = 0; j < 6; ++j) if (j < nf) dst[tid + j * 512] = pf[j];
            __syncthreads();
        }
    }

    // ============ attention: two independent 8-warp row-groups ============
    // grp0 (warps 0-7): m-tiles 0-3 (rows 0-63); grp1 (warps 8-15): m-tiles 4-6 (rows 64-97)
    const int g   = warp >> 3;
    const int wg  = warp & 7;
    const int mtbase = g ? 4 : 0;
    const int nmt = g ? 3 : 4;
    const int bar = g + 1;
    #define GBAR() asm volatile("bar.sync %0, 256;" :: "r"(bar) : "memory")

    // zero own rows' sa pad cols 98..103 (weight stage polluted the union)
    {
        int rbase = g ? 64 : 0;
        int rcnt  = g ? 34 : 64;
        for (int i = wg * 32 + lane; i < rcnt * 6; i += 256) {
            int r = rbase + i / 6, c = 98 + (i % 6);
            sa[r * SA_LD + c] = 0.f;
        }
    }

    for (int h = 0; h < 3; ++h) {
        // ---- scores: one job per warp = (m-tile, col-half) ----
        if (wg < nmt * 2) {
            int mt = mtbase + (wg >> 1);
            int cg = wg & 1;
            int ntb = cg * 7;
            int ntn = cg ? 6 : 7;
            const float* qb = sq + (mt * 16 + gid) * SQ_LD + h * 32 + tig;
            const float* kb = sk + gid * SK_LD + h * 32 + tig;
            float d[7][4];
            #pragma unroll
            for (int t = 0; t < 7; ++t) { d[t][0] = d[t][1] = d[t][2] = d[t][3] = 0.f; }
            #pragma unroll
            for (int c0 = 0; c0 < 32; c0 += 8) {
                float f0 = qb[c0], f1 = qb[8 * SQ_LD + c0];
                float f2 = qb[c0 + 4], f3 = qb[8 * SQ_LD + c0 + 4];
                unsigned h0 = t32(f0), h1 = t32(f1), h2 = t32(f2), h3 = t32(f3);
                unsigned l0 = t32(f0 - __uint_as_float(h0));
                unsigned l1 = t32(f1 - __uint_as_float(h1));
                unsigned l2 = t32(f2 - __uint_as_float(h2));
                unsigned l3 = t32(f3 - __uint_as_float(h3));
                #pragma unroll
                for (int t = 0; t < 7; ++t) {
                    if (t < ntn) {
                        const float* kp = kb + ((ntb + t) * 8) * SK_LD + c0;
                        unsigned b0 = __float_as_uint(kp[0]);
                        unsigned b1 = __float_as_uint(kp[4]);
                        mma8(d[t][0], d[t][1], d[t][2], d[t][3], h0, h1, h2, h3, b0, b1);
                        mma8(d[t][0], d[t][1], d[t][2], d[t][3], l0, l1, l2, l3, b0, b1);
                    }
                }
            }
            int r0 = mt * 16 + gid, r1 = r0 + 8;
            #pragma unroll
            for (int t = 0; t < 7; ++t) {
                if (t < ntn) {
                    int mc = (ntb + t) * 8 + 2 * tig;
                    if (mc < 98) {
                        const float* gbp = g_bias + h * 9800 + mc;
                        if (r0 < 98) {
                            float2 bv = *(const float2*)(gbp + r0 * 100);
                            *(float2*)(sa + r0 * SA_LD + mc) =
                                make_float2(d[t][0] * SCALEF + bv.x, d[t][1] * SCALEF + bv.y);
                        }
                        if (r1 < 98) {
                            float2 bv = *(const float2*)(gbp + r1 * 100);
                            *(float2*)(sa + r1 * SA_LD + mc) =
                                make_float2(d[t][2] * SCALEF + bv.x, d[t][3] * SCALEF + bv.y);
                        }
                    }
                }
            }
        }
        GBAR();

        // ---- softmax (warp per row, own rows only) ----
        {
            int rlo = g ? 64 : 0;
            int rhi = g ? 98 : 64;
            for (int r = rlo + wg; r < rhi; r += 8) {
                float* row = sa + r * SA_LD;
                float v0 = row[lane];
                float va = row[lane + 32];
                float vb = row[lane + 64];
                bool  g3 = (lane < 2);
                float vc = g3 ? row[lane + 96] : -1e30f;
                float mx = fmaxf(fmaxf(v0, va), fmaxf(vb, vc));
                #pragma unroll
                for (int s2 = 16; s2; s2 >>= 1) mx = fmaxf(mx, __shfl_xor_sync(~0u, mx, s2));
                float e0 = __expf(v0 - mx);
                float e1 = __expf(va - mx);
                float e2 = __expf(vb - mx);
                float e3 = g3 ? __expf(vc - mx) : 0.f;
                row[lane] = e0; row[lane + 32] = e1; row[lane + 64] = e2;
                if (g3) row[lane + 96] = e3;
                float s2s = e0 + e1 + e2 + e3;
                #pragma unroll
                for (int sh = 16; sh; sh >>= 1) s2s += __shfl_xor_sync(~0u, s2s, sh);
                if (lane == 0) ri[r] = 1.0f / s2s;
            }
        }
        GBAR();

        // ---- PV: one job per warp = (m-tile, n16-half) ----
        if (wg < nmt * 2) {
            int mt = mtbase + (wg >> 1), hf = wg & 1;
            const float* pb = sa + (mt * 16 + gid) * SA_LD + tig;
            const float* vp0 = sv + tig * SV_LD + h * 32 + hf * 16 + gid;
            float d[2][4];
            d[0][0] = d[0][1] = d[0][2] = d[0][3] = 0.f;
            d[1][0] = d[1][1] = d[1][2] = d[1][3] = 0.f;
            #pragma unroll
            for (int c0 = 0; c0 < 104; c0 += 8) {
                float f0 = pb[c0], f1 = pb[8 * SA_LD + c0];
                float f2 = pb[c0 + 4], f3 = pb[8 * SA_LD + c0 + 4];
                unsigned h0 = t32(f0), h1 = t32(f1), h2 = t32(f2), h3 = t32(f3);
                unsigned l0 = t32(f0 - __uint_as_float(h0));
                unsigned l1 = t32(f1 - __uint_as_float(h1));
                unsigned l2 = t32(f2 - __uint_as_float(h2));
                unsigned l3 = t32(f3 - __uint_as_float(h3));
                #pragma unroll
                for (int t = 0; t < 2; ++t) {
                    const float* vp = vp0 + c0 * SV_LD + t * 8;
                    unsigned b0 = __float_as_uint(vp[0]);
                    unsigned b1 = __float_as_uint(vp[4 * SV_LD]);
                    mma8(d[t][0], d[t][1], d[t][2], d[t][3], h0, h1, h2, h3, b0, b1);
                    mma8(d[t][0], d[t][1], d[t][2], d[t][3], l0, l1, l2, l3, b0, b1);
                }
            }
            int r0 = mt * 16 + gid, r1 = r0 + 8;
            int col = h * 32 + hf * 16 + 2 * tig;
            if (r0 < 98) {
                float rv = ri[r0];
                *(float2*)(sx + r0 * SX_LD + col)     = make_float2(d[0][0] * rv, d[0][1] * rv);
                *(float2*)(sx + r0 * SX_LD + col + 8) = make_float2(d[1][0] * rv, d[1][1] * rv);
            }
            if (r1 < 98) {
                float rv = ri[r1];
                *(float2*)(sx + r1 * SX_LD + col)     = make_float2(d[0][2] * rv, d[0][3] * rv);
                *(float2*)(sx + r1 * SX_LD + col + 8) = make_float2(d[1][2] * rv, d[1][3] * rv);
            }
        }
        GBAR();
    }
    __syncthreads();   // converge groups before proj (smW overlays sa)

    // ============ proj: out = attn_out @ proj_w^T + b; 2 stages ============
    float* ob = out + (size_t)b * 9408;
    {
        const float4* src = (const float4*)g_wp;
        #pragma unroll
        for (int j = 0; j < 6; ++j) pf[j] = src[tid + j * 512];
        float4* dst = (float4*)smW;
        #pragma unroll
        for (int j = 0; j < 6; ++j) dst[tid + j * 512] = pf[j];
    }
    __syncthreads();
    for (int s = 0; s < 2; ++s) {
        if (s == 0) {
            const float4* src = (const float4*)(g_wp + 12288);
            #pragma unroll
            for (int j = 0; j < 3; ++j) pf[j] = src[tid + j * 512];
        }
        int njobs = (s == 0) ? 14 : 7;
        if (warp < njobs) {
            int mt = warp % 7, chL = warp / 7;
            int chID = 2 * s + chL;
            const float* ap = sx + (mt * 16 + gid) * SX_LD + tig;
            const float* wp = smW + chL * 6144 + lane * 4;
            float d[4][4];
            #pragma unroll
            for (int t = 0; t < 4; ++t) { d[t][0] = d[t][1] = d[t][2] = d[t][3] = 0.f; }
            #pragma unroll
            for (int ks = 0; ks < 12; ++ks) {
                unsigned a0 = t32(ap[ks * 8]);
                unsigned a1 = t32(ap[8 * SX_LD + ks * 8]);
                unsigned a2 = t32(ap[ks * 8 + 4]);
                unsigned a3 = t32(ap[8 * SX_LD + ks * 8 + 4]);
                #pragma unroll
                for (int t = 0; t < 4; ++t) {
                    float4 w4 = *(const float4*)(wp + ks * 512 + t * 128);
                    mma8(d[t][0], d[t][1], d[t][2], d[t][3], a0, a1, a2, a3,
                         __float_as_uint(w4.x), __float_as_uint(w4.y));
                    mma8(d[t][0], d[t][1], d[t][2], d[t][3], a0, a1, a2, a3,
                         __float_as_uint(w4.z), __float_as_uint(w4.w));
                }
            }
            int r0 = mt * 16 + gid, r1 = r0 + 8;
            int j0 = chID * 32;
            #pragma unroll
            for (int t = 0; t < 4; ++t) {
                int j = j0 + t * 8 + 2 * tig;
                float2 bb = *(const float2*)(proj_b + j);
                if (r0 < 98) *(float2*)(ob + r0 * 96 + j) =
                    make_float2(d[t][0] + bb.x, d[t][1] + bb.y);
                if (r1 < 98) *(float2*)(ob + r1 * 96 + j) =
                    make_float2(d[t][2] + bb.x, d[t][3] + bb.y);
            }
        }
        __syncthreads();
        if (s == 0) {
            float4* dst = (float4*)smW;
            #pragma unroll
            for (int j = 0; j < 3; ++j) dst[tid + j * 512] = pf[j];
            __syncthreads();
        }
    }
}

extern "C" void kernel_launch(void* const* d_in, const int* in_sizes, int n_in,
                              void* d_out, int out_size)
{
    const float* x          = (const float*)d_in[0];
    const float* qkv_w      = (const float*)d_in[1];
    const float* qkv_b      = (const float*)d_in[2];
    const float* proj_w     = (const float*)d_in[3];
    const float* proj_b     = (const float*)d_in[4];
    const float* bias_table = (const float*)d_in[5];
    const int*   rel_index  = (const int*)d_in[6];
    float* out = (float*)d_out;

    int prep_total = 18432 + 29400;
    prep_kernel<<<(prep_total + 255) / 256, 256>>>(qkv_w, proj_w, bias_table, rel_index);

    cudaFuncSetAttribute(wa3d_main, cudaFuncAttributeMaxDynamicSharedMemorySize, SMEM_BYTES);
    wa3d_main<<<4096, NT, SMEM_BYTES>>>(x, qkv_b, proj_b, out);
}

// round 12
// speedup vs baseline: 1.9339x; 1.0878x over previous
#include <cuda_runtime.h>

#define NT 512
#define SCALEF 0.17677669529663687f   // 1/sqrt(32)

// smem strides (floats) — conflict-free for the MMA frag patterns
#define SX_LD 100   // A-pattern: 100%32=4
#define SQ_LD 100
#define SK_LD 100   // scores B-pattern (K stored [m][d])
#define SV_LD 104   // PV B-pattern: 104%32=8
#define SA_LD 108   // PV A-pattern: 108%32=12

// region offsets (floats)
#define OFF_SX  0        // [98][100] = 9800
#define OFF_SQ  9800     // [98][100]
#define OFF_SK  19600    // [104][100] (rows 98..103 zeroed)
#define OFF_SV  30000    // [104][104] (rows 98..103 zeroed)
#define OFF_SAW 40816    // union: sa [98][108] / weight stage 12288
#define OFF_HM  53104    // half-row max [98][2] -> 200
#define OFF_HS  53304    // half-row sum [98][2] -> 200
#define SMEM_FLOATS 53504
#define SMEM_BYTES (SMEM_FLOATS * 4)   // 214,016 B

__device__ float g_w1[9 * 6144];       // GEMM1 weights: frag-permuted, hi/lo split
__device__ float g_wp[3 * 6144];       // proj weights: same layout
__device__ float g_bias[3 * 98 * 100]; // bias[h][n][m], m padded to 100 (pad=0)

__device__ __forceinline__ unsigned t32(float f) {
    unsigned u; asm("cvt.rna.tf32.f32 %0, %1;" : "=r"(u) : "f"(f)); return u;
}
__device__ __forceinline__ void mma8(float& d0, float& d1, float& d2, float& d3,
                                     unsigned a0, unsigned a1, unsigned a2, unsigned a3,
                                     unsigned b0, unsigned b1) {
    asm volatile(
        "mma.sync.aligned.m16n8k8.row.col.f32.tf32.tf32.f32 "
        "{%0,%1,%2,%3},{%4,%5,%6,%7},{%8,%9},{%0,%1,%2,%3};"
        : "+f"(d0), "+f"(d1), "+f"(d2), "+f"(d3)
        : "r"(a0), "r"(a1), "r"(a2), "r"(a3), "r"(b0), "r"(b1));
}

// ---- prep: frag-permuted pre-split weights + padded bias ----
__global__ void prep_kernel(const float* __restrict__ qkv_w,
                            const float* __restrict__ proj_w,
                            const float* __restrict__ table,
                            const int* __restrict__ rel)
{
    int i = blockIdx.x * blockDim.x + threadIdx.x;
    if (i < 13824) {
        int lane = i & 31, tk = i >> 5;
        int ch = tk / 48, rem = tk - ch * 48;
        int ks = rem >> 2, t = rem & 3;
        int gid = lane >> 2, tig = lane & 3;
        int col = ch * 32 + t * 8 + gid, c = ks * 8 + tig;
        float w0 = qkv_w[col * 96 + c], w1 = qkv_w[col * 96 + c + 4];
        float4 v;
        v.x = __uint_as_float(t32(w0)); v.y = __uint_as_float(t32(w1));
        v.z = __uint_as_float(t32(w0 - v.x)); v.w = __uint_as_float(t32(w1 - v.y));
        ((float4*)g_w1)[i] = v;
    } else if (i < 18432) {
        int q = i - 13824;
        int lane = q & 31, tk = q >> 5;
        int ch = tk / 48, rem = tk - ch * 48;
        int ks = rem >> 2, t = rem & 3;
        int gid = lane >> 2, tig = lane & 3;
        int col = ch * 32 + t * 8 + gid, c = ks * 8 + tig;
        float w0 = proj_w[col * 96 + c], w1 = proj_w[col * 96 + c + 4];
        float4 v;
        v.x = __uint_as_float(t32(w0)); v.y = __uint_as_float(t32(w1));
        v.z = __uint_as_float(t32(w0 - v.x)); v.w = __uint_as_float(t32(w1 - v.y));
        ((float4*)g_wp)[q] = v;
    } else if (i < 18432 + 29400) {
        int k = i - 18432;
        int h = k / 9800, r = k - h * 9800;
        int n = r / 100, m = r - n * 100;
        g_bias[k] = (m < 98) ? table[rel[n * 98 + m] * 3 + h] : 0.f;
    }
}

__global__ void __launch_bounds__(NT, 1)
wa3d_main(const float* __restrict__ x, const float* __restrict__ qkv_b,
          const float* __restrict__ proj_b, float* __restrict__ out)
{
    extern __shared__ float sm[];
    float* sx  = sm + OFF_SX;    // x (tf32-rounded), later attn_out (tf32-rounded)
    float* sq  = sm + OFF_SQ;    // q fp32 [m][96]
    float* sk  = sm + OFF_SK;    // k tf32-bits [m][96]
    float* sv  = sm + OFF_SV;    // v tf32-bits [m][96]
    float* sa  = sm + OFF_SAW;   // probs (union with weight stage)
    float* smW = sm + OFF_SAW;
    float* hm  = sm + OFF_HM;    // half-row max [98][2]
    float* hs  = sm + OFF_HS;    // half-row sum [98][2]

    const int b    = blockIdx.x;
    const int tid  = threadIdx.x;
    const int warp = tid >> 5, lane = tid & 31;
    const int gid  = lane >> 2;   // 0..7
    const int tig  = lane & 3;    // 0..3

    float4 pf[6];

    // ---- prefetch weight stage 0 ----
    {
        const float4* src = (const float4*)g_w1;
        #pragma unroll
        for (int j = 0; j < 6; ++j) pf[j] = src[tid + j * 512];
    }
    // ---- zero pad strips (k/v rows 98..103) ----
    for (int i = tid; i < 600; i += NT) sk[9800 + i] = 0.f;
    for (int i = tid; i < 624; i += NT) sv[10192 + i] = 0.f;
    // ---- stage x[b], tf32-rounded (GEMM1 A is single-rounded anyway) ----
    const float* xb = x + (size_t)b * 9408;
    for (int i = tid; i < 9408; i += NT) {
        int r = i / 96, c = i - r * 96;
        sx[r * SX_LD + c] = __uint_as_float(t32(xb[i]));
    }
    // ---- store weight stage 0 ----
    {
        float4* dst = (float4*)smW;
        #pragma unroll
        for (int j = 0; j < 6; ++j) dst[tid + j * 512] = pf[j];
    }
    __syncthreads();

    // ============ GEMM1: qkv = x @ qkv_w^T + b; 5 stages ============
    for (int s = 0; s < 5; ++s) {
        if (s < 4) {
            int nf = (s == 3) ? 3 : 6;
            const float4* src = (const float4*)(g_w1 + (s + 1) * 12288);
            #pragma unroll
            for (int j = 0; j < 6; ++j) if (j < nf) pf[j] = src[tid + j * 512];
        }
        int njobs = (s < 4) ? 14 : 7;
        if (warp < njobs) {
            int mt = warp % 7, chL = warp / 7;
            int chID = 2 * s + chL;
            const float* ap = sx + (mt * 16 + gid) * SX_LD + tig;
            const float* wp = smW + chL * 6144 + lane * 4;
            float d[4][4];
            #pragma unroll
            for (int t = 0; t < 4; ++t) { d[t][0] = d[t][1] = d[t][2] = d[t][3] = 0.f; }
            #pragma unroll
            for (int ks = 0; ks < 12; ++ks) {
                unsigned a0 = __float_as_uint(ap[ks * 8]);
                unsigned a1 = __float_as_uint(ap[8 * SX_LD + ks * 8]);
                unsigned a2 = __float_as_uint(ap[ks * 8 + 4]);
                unsigned a3 = __float_as_uint(ap[8 * SX_LD + ks * 8 + 4]);
                #pragma unroll
                for (int t = 0; t < 4; ++t) {
                    float4 w4 = *(const float4*)(wp + ks * 512 + t * 128);
                    mma8(d[t][0], d[t][1], d[t][2], d[t][3], a0, a1, a2, a3,
                         __float_as_uint(w4.x), __float_as_uint(w4.y));
                    mma8(d[t][0], d[t][1], d[t][2], d[t][3], a0, a1, a2, a3,
                         __float_as_uint(w4.z), __float_as_uint(w4.w));
                }
            }
            int r0 = mt * 16 + gid, r1 = r0 + 8;
            int j0 = chID * 32;
            #pragma unroll
            for (int t = 0; t < 4; ++t) {
                int j = j0 + t * 8 + 2 * tig;
                float2 bb = *(const float2*)(qkv_b + j);
                float v00 = d[t][0] + bb.x, v01 = d[t][1] + bb.y;
                float v10 = d[t][2] + bb.x, v11 = d[t][3] + bb.y;
                if (chID < 3) {
                    if (r0 < 98) *(float2*)(sq + r0 * SQ_LD + j) = make_float2(v00, v01);
                    if (r1 < 98) *(float2*)(sq + r1 * SQ_LD + j) = make_float2(v10, v11);
                } else if (chID < 6) {
                    int jj = j - 96;
                    if (r0 < 98) *(float2*)(sk + r0 * SK_LD + jj) =
                        make_float2(__uint_as_float(t32(v00)), __uint_as_float(t32(v01)));
                    if (r1 < 98) *(float2*)(sk + r1 * SK_LD + jj) =
                        make_float2(__uint_as_float(t32(v10)), __uint_as_float(t32(v11)));
                } else {
                    int jj = j - 192;
                    if (r0 < 98) *(float2*)(sv + r0 * SV_LD + jj) =
                        make_float2(__uint_as_float(t32(v00)), __uint_as_float(t32(v01)));
                    if (r1 < 98) *(float2*)(sv + r1 * SV_LD + jj) =
                        make_float2(__uint_as_float(t32(v10)), __uint_as_float(t32(v11)));
                }
            }
        }
        __syncthreads();
        if (s < 4) {
            int nf = (s == 3) ? 3 : 6;
            float4* dst = (float4*)smW;
            #pragma unroll
            for (int j = 0; j < 6; ++j) if (j < nf) dst[tid + j * 512] = pf[j];
            __syncthreads();
        }
    }

    // ============ attention: two independent 8-warp row-groups ============
    const int g   = warp >> 3;
    const int wg  = warp & 7;
    const int mtbase = g ? 4 : 0;
    const int nmt = g ? 3 : 4;
    const int bar = g + 1;
    #define GBAR() asm volatile("bar.sync %0, 256;" :: "r"(bar) : "memory")

    // zero own rows' sa pad cols 98..103 (weight stage polluted the union)
    {
        int rbase = g ? 64 : 0;
        int rcnt  = g ? 34 : 64;
        for (int i = wg * 32 + lane; i < rcnt * 6; i += 256) {
            int r = rbase + i / 6, c = 98 + (i % 6);
            sa[r * SA_LD + c] = 0.f;
        }
    }

    for (int h = 0; h < 3; ++h) {
        // ---- scores + fused softmax: one job per warp = (m-tile, col-half) ----
        if (wg < nmt * 2) {
            int mt = mtbase + (wg >> 1);
            int cg = wg & 1;
            int ntb = cg * 7;
            int ntn = cg ? 6 : 7;
            const float* qb = sq + (mt * 16 + gid) * SQ_LD + h * 32 + tig;
            const float* kb = sk + gid * SK_LD + h * 32 + tig;
            float d[7][4];
            #pragma unroll
            for (int t = 0; t < 7; ++t) { d[t][0] = d[t][1] = d[t][2] = d[t][3] = 0.f; }
            #pragma unroll
            for (int c0 = 0; c0 < 32; c0 += 8) {
                float f0 = qb[c0], f1 = qb[8 * SQ_LD + c0];
                float f2 = qb[c0 + 4], f3 = qb[8 * SQ_LD + c0 + 4];
                unsigned h0 = t32(f0), h1 = t32(f1), h2 = t32(f2), h3 = t32(f3);
                unsigned l0 = t32(f0 - __uint_as_float(h0));
                unsigned l1 = t32(f1 - __uint_as_float(h1));
                unsigned l2 = t32(f2 - __uint_as_float(h2));
                unsigned l3 = t32(f3 - __uint_as_float(h3));
                #pragma unroll
                for (int t = 0; t < 7; ++t) {
                    if (t < ntn) {
                        const float* kp = kb + ((ntb + t) * 8) * SK_LD + c0;
                        unsigned b0 = __float_as_uint(kp[0]);
                        unsigned b1 = __float_as_uint(kp[4]);
                        mma8(d[t][0], d[t][1], d[t][2], d[t][3], h0, h1, h2, h3, b0, b1);
                        mma8(d[t][0], d[t][1], d[t][2], d[t][3], l0, l1, l2, l3, b0, b1);
                    }
                }
            }
            int r0 = mt * 16 + gid, r1 = r0 + 8;
            bool rv0 = (r0 < 98), rv1 = (r1 < 98);
            // s = scale*qk + bias (kept in d[]), half-row max
            float m0 = -1e30f, m1 = -1e30f;
            #pragma unroll
            for (int t = 0; t < 7; ++t) {
                if (t < ntn) {
                    int mc = (ntb + t) * 8 + 2 * tig;
                    if (mc < 98) {
                        const float* gbp = g_bias + h * 9800 + mc;
                        if (rv0) {
                            float2 bv = *(const float2*)(gbp + r0 * 100);
                            d[t][0] = d[t][0] * SCALEF + bv.x;
                            d[t][1] = d[t][1] * SCALEF + bv.y;
                            m0 = fmaxf(m0, fmaxf(d[t][0], d[t][1]));
                        }
                        if (rv1) {
                            float2 bv = *(const float2*)(gbp + r1 * 100);
                            d[t][2] = d[t][2] * SCALEF + bv.x;
                            d[t][3] = d[t][3] * SCALEF + bv.y;
                            m1 = fmaxf(m1, fmaxf(d[t][2], d[t][3]));
                        }
                    }
                }
            }
            m0 = fmaxf(m0, __shfl_xor_sync(~0u, m0, 1));
            m0 = fmaxf(m0, __shfl_xor_sync(~0u, m0, 2));
            m1 = fmaxf(m1, __shfl_xor_sync(~0u, m1, 1));
            m1 = fmaxf(m1, __shfl_xor_sync(~0u, m1, 2));
            if (tig == 0) {
                if (rv0) hm[r0 * 2 + cg] = m0;
                if (rv1) hm[r1 * 2 + cg] = m1;
            }
            // exchange half maxes between the pair of warps sharing this m-tile
            asm volatile("bar.sync %0, 64;" :: "r"(3 + mt) : "memory");
            float gm0 = 0.f, gm1 = 0.f;
            if (rv0) { float2 t2 = *(const float2*)(hm + r0 * 2); gm0 = fmaxf(t2.x, t2.y); }
            if (rv1) { float2 t2 = *(const float2*)(hm + r1 * 2); gm1 = fmaxf(t2.x, t2.y); }
            float s0 = 0.f, s1 = 0.f;
            #pragma unroll
            for (int t = 0; t < 7; ++t) {
                if (t < ntn) {
                    int mc = (ntb + t) * 8 + 2 * tig;
                    if (mc < 98) {
                        if (rv0) {
                            float e0 = __expf(d[t][0] - gm0);
                            float e1 = __expf(d[t][1] - gm0);
                            s0 += e0 + e1;
                            *(float2*)(sa + r0 * SA_LD + mc) = make_float2(e0, e1);
                        }
                        if (rv1) {
                            float e0 = __expf(d[t][2] - gm1);
                            float e1 = __expf(d[t][3] - gm1);
                            s1 += e0 + e1;
                            *(float2*)(sa + r1 * SA_LD + mc) = make_float2(e0, e1);
                        }
                    }
                }
            }
            s0 += __shfl_xor_sync(~0u, s0, 1);
            s0 += __shfl_xor_sync(~0u, s0, 2);
            s1 += __shfl_xor_sync(~0u, s1, 1);
            s1 += __shfl_xor_sync(~0u, s1, 2);
            if (tig == 0) {
                if (rv0) hs[r0 * 2 + cg] = s0;
                if (rv1) hs[r1 * 2 + cg] = s1;
            }
        }
        GBAR();

        // ---- PV: one job per warp = (m-tile, n16-half) ----
        if (wg < nmt * 2) {
            int mt = mtbase + (wg >> 1), hf = wg & 1;
            const float* pb = sa + (mt * 16 + gid) * SA_LD + tig;
            const float* vp0 = sv + tig * SV_LD + h * 32 + hf * 16 + gid;
            float d[2][4];
            d[0][0] = d[0][1] = d[0][2] = d[0][3] = 0.f;
            d[1][0] = d[1][1] = d[1][2] = d[1][3] = 0.f;
            #pragma unroll
            for (int c0 = 0; c0 < 104; c0 += 8) {
                float f0 = pb[c0], f1 = pb[8 * SA_LD + c0];
                float f2 = pb[c0 + 4], f3 = pb[8 * SA_LD + c0 + 4];
                unsigned h0 = t32(f0), h1 = t32(f1), h2 = t32(f2), h3 = t32(f3);
                unsigned l0 = t32(f0 - __uint_as_float(h0));
                unsigned l1 = t32(f1 - __uint_as_float(h1));
                unsigned l2 = t32(f2 - __uint_as_float(h2));
                unsigned l3 = t32(f3 - __uint_as_float(h3));
                #pragma unroll
                for (int t = 0; t < 2; ++t) {
                    const float* vp = vp0 + c0 * SV_LD + t * 8;
                    unsigned b0 = __float_as_uint(vp[0]);
                    unsigned b1 = __float_as_uint(vp[4 * SV_LD]);
                    mma8(d[t][0], d[t][1], d[t][2], d[t][3], h0, h1, h2, h3, b0, b1);
                    mma8(d[t][0], d[t][1], d[t][2], d[t][3], l0, l1, l2, l3, b0, b1);
                }
            }
            int r0 = mt * 16 + gid, r1 = r0 + 8;
            int col = h * 32 + hf * 16 + 2 * tig;
            if (r0 < 98) {
                float2 h2 = *(const float2*)(hs + r0 * 2);
                float rv = __fdividef(1.f, h2.x + h2.y);
                *(float2*)(sx + r0 * SX_LD + col) = make_float2(
                    __uint_as_float(t32(d[0][0] * rv)), __uint_as_float(t32(d[0][1] * rv)));
                *(float2*)(sx + r0 * SX_LD + col + 8) = make_float2(
                    __uint_as_float(t32(d[1][0] * rv)), __uint_as_float(t32(d[1][1] * rv)));
            }
            if (r1 < 98) {
                float2 h2 = *(const float2*)(hs + r1 * 2);
                float rv = __fdividef(1.f, h2.x + h2.y);
                *(float2*)(sx + r1 * SX_LD + col) = make_float2(
                    __uint_as_float(t32(d[0][2] * rv)), __uint_as_float(t32(d[0][3] * rv)));
                *(float2*)(sx + r1 * SX_LD + col + 8) = make_float2(
                    __uint_as_float(t32(d[1][2] * rv)), __uint_as_float(t32(d[1][3] * rv)));
            }
        }
        GBAR();
    }
    __syncthreads();   // converge groups before proj (smW overlays sa)

    // ============ proj: out = attn_out @ proj_w^T + b; 2 stages ============
    float* ob = out + (size_t)b * 9408;
    {
        const float4* src = (const float4*)g_wp;
        #pragma unroll
        for (int j = 0; j < 6; ++j) pf[j] = src[tid + j * 512];
        float4* dst = (float4*)smW;
        #pragma unroll
        for (int j = 0; j < 6; ++j) dst[tid + j * 512] = pf[j];
    }
    __syncthreads();
    for (int s = 0; s < 2; ++s) {
        if (s == 0) {
            const float4* src = (const float4*)(g_wp + 12288);
            #pragma unroll
            for (int j = 0; j < 3; ++j) pf[j] = src[tid + j * 512];
        }
        int njobs = (s == 0) ? 14 : 7;
        if (warp < njobs) {
            int mt = warp % 7, chL = warp / 7;
            int chID = 2 * s + chL;
            const float* ap = sx + (mt * 16 + gid) * SX_LD + tig;
            const float* wp = smW + chL * 6144 + lane * 4;
            float d[4][4];
            #pragma unroll
            for (int t = 0; t < 4; ++t) { d[t][0] = d[t][1] = d[t][2] = d[t][3] = 0.f; }
            #pragma unroll
            for (int ks = 0; ks < 12; ++ks) {
                unsigned a0 = __float_as_uint(ap[ks * 8]);
                unsigned a1 = __float_as_uint(ap[8 * SX_LD + ks * 8]);
                unsigned a2 = __float_as_uint(ap[ks * 8 + 4]);
                unsigned a3 = __float_as_uint(ap[8 * SX_LD + ks * 8 + 4]);
                #pragma unroll
                for (int t = 0; t < 4; ++t) {
                    float4 w4 = *(const float4*)(wp + ks * 512 + t * 128);
                    mma8(d[t][0], d[t][1], d[t][2], d[t][3], a0, a1, a2, a3,
                         __float_as_uint(w4.x), __float_as_uint(w4.y));
                    mma8(d[t][0], d[t][1], d[t][2], d[t][3], a0, a1, a2, a3,
                         __float_as_uint(w4.z), __float_as_uint(w4.w));
                }
            }
            int r0 = mt * 16 + gid, r1 = r0 + 8;
            int j0 = chID * 32;
            #pragma unroll
            for (int t = 0; t < 4; ++t) {
                int j = j0 + t * 8 + 2 * tig;
                float2 bb = *(const float2*)(proj_b + j);
                if (r0 < 98) *(float2*)(ob + r0 * 96 + j) =
                    make_float2(d[t][0] + bb.x, d[t][1] + bb.y);
                if (r1 < 98) *(float2*)(ob + r1 * 96 + j) =
                    make_float2(d[t][2] + bb.x, d[t][3] + bb.y);
            }
        }
        __syncthreads();
        if (s == 0) {
            float4* dst = (float4*)smW;
            #pragma unroll
            for (int j = 0; j < 3; ++j) dst[tid + j * 512] = pf[j];
            __syncthreads();
        }
    }
}

extern "C" void kernel_launch(void* const* d_in, const int* in_sizes, int n_in,
                              void* d_out, int out_size)
{
    const float* x          = (const float*)d_in[0];
    const float* qkv_w      = (const float*)d_in[1];
    const float* qkv_b      = (const float*)d_in[2];
    const float* proj_w     = (const float*)d_in[3];
    const float* proj_b     = (const float*)d_in[4];
    const float* bias_table = (const float*)d_in[5];
    const int*   rel_index  = (const int*)d_in[6];
    float* out = (float*)d_out;

    int prep_total = 18432 + 29400;
    prep_kernel<<<(prep_total + 255) / 256, 256>>>(qkv_w, proj_w, bias_table, rel_index);

    cudaFuncSetAttribute(wa3d_main, cudaFuncAttributeMaxDynamicSharedMemorySize, SMEM_BYTES);
    wa3d_main<<<4096, NT, SMEM_BYTES>>>(x, qkv_b, proj_b, out);
}

// round 13
// speedup vs baseline: 2.2614x; 1.1694x over previous
#include <cuda_runtime.h>

#define NT 512
#define SCALEF 0.17677669529663687f   // 1/sqrt(32)

// smem strides (floats) — conflict-free for the MMA frag patterns
#define SX_LD 100   // A-pattern: 100%32=4
#define SQ_LD 100
#define SK_LD 100   // scores B-pattern (K stored [m][d])
#define SV_LD 104   // PV B-pattern: 104%32=8 (rows stored PERMUTED for reg-direct PV)

// region offsets (floats)
#define OFF_SX  0        // [98][100] = 9800
#define OFF_SQ  9800     // [98][100]
#define OFF_SK  19600    // [104][100] (rows 98..103 zeroed)
#define OFF_SV  30000    // [104][104] (position-rows 97..103 zeroed)
#define OFF_SAW 40816    // weight stage 12288
#define SMEM_FLOATS 53104
#define SMEM_BYTES (SMEM_FLOATS * 4)   // 212,416 B

__device__ float g_w1[9 * 6144];       // GEMM1 weights: frag-permuted, hi/lo split
__device__ float g_wp[3 * 6144];       // proj weights: same layout
__device__ float g_bias[3 * 98 * 100]; // bias[h][n][m], m padded to 100 (pad=0)

__device__ __forceinline__ unsigned t32(float f) {
    unsigned u; asm("cvt.rna.tf32.f32 %0, %1;" : "=r"(u) : "f"(f)); return u;
}
__device__ __forceinline__ void mma8(float& d0, float& d1, float& d2, float& d3,
                                     unsigned a0, unsigned a1, unsigned a2, unsigned a3,
                                     unsigned b0, unsigned b1) {
    asm volatile(
        "mma.sync.aligned.m16n8k8.row.col.f32.tf32.tf32.f32 "
        "{%0,%1,%2,%3},{%4,%5,%6,%7},{%8,%9},{%0,%1,%2,%3};"
        : "+f"(d0), "+f"(d1), "+f"(d2), "+f"(d3)
        : "r"(a0), "r"(a1), "r"(a2), "r"(a3), "r"(b0), "r"(b1));
}

// ---- prep: frag-permuted pre-split weights + padded bias ----
__global__ void prep_kernel(const float* __restrict__ qkv_w,
                            const float* __restrict__ proj_w,
                            const float* __restrict__ table,
                            const int* __restrict__ rel)
{
    int i = blockIdx.x * blockDim.x + threadIdx.x;
    if (i < 13824) {
        int lane = i & 31, tk = i >> 5;
        int ch = tk / 48, rem = tk - ch * 48;
        int ks = rem >> 2, t = rem & 3;
        int gid = lane >> 2, tig = lane & 3;
        int col = ch * 32 + t * 8 + gid, c = ks * 8 + tig;
        float w0 = qkv_w[col * 96 + c], w1 = qkv_w[col * 96 + c + 4];
        float4 v;
        v.x = __uint_as_float(t32(w0)); v.y = __uint_as_float(t32(w1));
        v.z = __uint_as_float(t32(w0 - v.x)); v.w = __uint_as_float(t32(w1 - v.y));
        ((float4*)g_w1)[i] = v;
    } else if (i < 18432) {
        int q = i - 13824;
        int lane = q & 31, tk = q >> 5;
        int ch = tk / 48, rem = tk - ch * 48;
        int ks = rem >> 2, t = rem & 3;
        int gid = lane >> 2, tig = lane & 3;
        int col = ch * 32 + t * 8 + gid, c = ks * 8 + tig;
        float w0 = proj_w[col * 96 + c], w1 = proj_w[col * 96 + c + 4];
        float4 v;
        v.x = __uint_as_float(t32(w0)); v.y = __uint_as_float(t32(w1));
        v.z = __uint_as_float(t32(w0 - v.x)); v.w = __uint_as_float(t32(w1 - v.y));
        ((float4*)g_wp)[q] = v;
    } else if (i < 18432 + 29400) {
        int k = i - 18432;
        int h = k / 9800, r = k - h * 9800;
        int n = r / 100, m = r - n * 100;
        g_bias[k] = (m < 98) ? table[rel[n * 98 + m] * 3 + h] : 0.f;
    }
}

__global__ void __launch_bounds__(NT, 1)
wa3d_main(const float* __restrict__ x, const float* __restrict__ qkv_b,
          const float* __restrict__ proj_b, float* __restrict__ out)
{
    extern __shared__ float sm[];
    float* sx  = sm + OFF_SX;    // x (tf32-rounded), later attn_out (tf32-rounded)
    float* sq  = sm + OFF_SQ;    // q fp32 [m][96]
    float* sk  = sm + OFF_SK;    // k tf32-bits [m][96]
    float* sv  = sm + OFF_SV;    // v tf32-bits, ROW-PERMUTED [pos][96]
    float* smW = sm + OFF_SAW;   // weight stage

    const int b    = blockIdx.x;
    const int tid  = threadIdx.x;
    const int warp = tid >> 5, lane = tid & 31;
    const int gid  = lane >> 2;   // 0..7
    const int tig  = lane & 3;    // 0..3

    float4 pf[6];

    // ---- prefetch weight stage 0 ----
    {
        const float4* src = (const float4*)g_w1;
        #pragma unroll
        for (int j = 0; j < 6; ++j) pf[j] = src[tid + j * 512];
    }
    // ---- zero pad strips: sk rows 98..103, sv position-rows 97..103 ----
    for (int i = tid; i < 600; i += NT) sk[9800 + i] = 0.f;
    for (int i = tid; i < 728; i += NT) sv[10088 + i] = 0.f;
    // ---- stage x[b], tf32-rounded ----
    const float* xb = x + (size_t)b * 9408;
    for (int i = tid; i < 9408; i += NT) {
        int r = i / 96, c = i - r * 96;
        sx[r * SX_LD + c] = __uint_as_float(t32(xb[i]));
    }
    // ---- store weight stage 0 ----
    {
        float4* dst = (float4*)smW;
        #pragma unroll
        for (int j = 0; j < 6; ++j) dst[tid + j * 512] = pf[j];
    }
    __syncthreads();

    // ============ GEMM1: qkv = x @ qkv_w^T + b; 5 stages ============
    for (int s = 0; s < 5; ++s) {
        if (s < 4) {
            int nf = (s == 3) ? 3 : 6;
            const float4* src = (const float4*)(g_w1 + (s + 1) * 12288);
            #pragma unroll
            for (int j = 0; j < 6; ++j) if (j < nf) pf[j] = src[tid + j * 512];
        }
        int njobs = (s < 4) ? 14 : 7;
        if (warp < njobs) {
            int mt = warp % 7, chL = warp / 7;
            int chID = 2 * s + chL;
            const float* ap = sx + (mt * 16 + gid) * SX_LD + tig;
            const float* wp = smW + chL * 6144 + lane * 4;
            float d[4][4];
            #pragma unroll
            for (int t = 0; t < 4; ++t) { d[t][0] = d[t][1] = d[t][2] = d[t][3] = 0.f; }
            #pragma unroll
            for (int ks = 0; ks < 12; ++ks) {
                unsigned a0 = __float_as_uint(ap[ks * 8]);
                unsigned a1 = __float_as_uint(ap[8 * SX_LD + ks * 8]);
                unsigned a2 = __float_as_uint(ap[ks * 8 + 4]);
                unsigned a3 = __float_as_uint(ap[8 * SX_LD + ks * 8 + 4]);
                #pragma unroll
                for (int t = 0; t < 4; ++t) {
                    float4 w4 = *(const float4*)(wp + ks * 512 + t * 128);
                    mma8(d[t][0], d[t][1], d[t][2], d[t][3], a0, a1, a2, a3,
                         __float_as_uint(w4.x), __float_as_uint(w4.y));
                    mma8(d[t][0], d[t][1], d[t][2], d[t][3], a0, a1, a2, a3,
                         __float_as_uint(w4.z), __float_as_uint(w4.w));
                }
            }
            int r0 = mt * 16 + gid, r1 = r0 + 8;
            int j0 = chID * 32;
            // permuted row index for V: p-block layout so PV can consume probs in-register
            int pr0 = 8 * (r0 >> 3) + ((r0 & 1) << 2) + ((r0 & 7) >> 1);
            int pr1 = 8 * (r1 >> 3) + ((r1 & 1) << 2) + ((r1 & 7) >> 1);
            #pragma unroll
            for (int t = 0; t < 4; ++t) {
                int j = j0 + t * 8 + 2 * tig;
                float2 bb = *(const float2*)(qkv_b + j);
                float v00 = d[t][0] + bb.x, v01 = d[t][1] + bb.y;
                float v10 = d[t][2] + bb.x, v11 = d[t][3] + bb.y;
                if (chID < 3) {
                    if (r0 < 98) *(float2*)(sq + r0 * SQ_LD + j) = make_float2(v00, v01);
                    if (r1 < 98) *(float2*)(sq + r1 * SQ_LD + j) = make_float2(v10, v11);
                } else if (chID < 6) {
                    int jj = j - 96;
                    if (r0 < 98) *(float2*)(sk + r0 * SK_LD + jj) =
                        make_float2(__uint_as_float(t32(v00)), __uint_as_float(t32(v01)));
                    if (r1 < 98) *(float2*)(sk + r1 * SK_LD + jj) =
                        make_float2(__uint_as_float(t32(v10)), __uint_as_float(t32(v11)));
                } else {
                    int jj = j - 192;
                    if (r0 < 98) *(float2*)(sv + pr0 * SV_LD + jj) =
                        make_float2(__uint_as_float(t32(v00)), __uint_as_float(t32(v01)));
                    if (r1 < 98) *(float2*)(sv + pr1 * SV_LD + jj) =
                        make_float2(__uint_as_float(t32(v10)), __uint_as_float(t32(v11)));
                }
            }
        }
        __syncthreads();
        if (s < 4) {
            int nf = (s == 3) ? 3 : 6;
            float4* dst = (float4*)smW;
            #pragma unroll
            for (int j = 0; j < 6; ++j) if (j < nf) dst[tid + j * 512] = pf[j];
            __syncthreads();
        }
    }

    // ============ attention: fully fused, zero barriers; 21 jobs / 16 warps ============
    for (int job = warp; job < 21; job += 16) {
        int h = job / 7, mt = job - h * 7;
        int r0 = mt * 16 + gid, r1 = r0 + 8;

        // ---- scores: Q(split) x K(tf32), full 98-col row in registers ----
        float d[13][4];
        #pragma unroll
        for (int t = 0; t < 13; ++t) { d[t][0] = d[t][1] = d[t][2] = d[t][3] = 0.f; }
        {
            const float* qb = sq + r0 * SQ_LD + h * 32 + tig;
            const float* kb = sk + gid * SK_LD + h * 32 + tig;
            #pragma unroll
            for (int c0 = 0; c0 < 32; c0 += 8) {
                float f0 = qb[c0], f1 = qb[8 * SQ_LD + c0];
                float f2 = qb[c0 + 4], f3 = qb[8 * SQ_LD + c0 + 4];
                unsigned h0 = t32(f0), h1 = t32(f1), h2 = t32(f2), h3 = t32(f3);
                unsigned l0 = t32(f0 - __uint_as_float(h0));
                unsigned l1 = t32(f1 - __uint_as_float(h1));
                unsigned l2 = t32(f2 - __uint_as_float(h2));
                unsigned l3 = t32(f3 - __uint_as_float(h3));
                #pragma unroll
                for (int t = 0; t < 13; ++t) {
                    const float* kp = kb + (t * 8) * SK_LD + c0;
                    unsigned b0 = __float_as_uint(kp[0]);
                    unsigned b1 = __float_as_uint(kp[4]);
                    mma8(d[t][0], d[t][1], d[t][2], d[t][3], h0, h1, h2, h3, b0, b1);
                    mma8(d[t][0], d[t][1], d[t][2], d[t][3], l0, l1, l2, l3, b0, b1);
                }
            }
        }

        // ---- bias + mask + in-register softmax (unnormalized) ----
        const float* gb = g_bias + h * 9800;
        int rb0 = min(r0, 97) * 100, rb1 = min(r1, 97) * 100;
        float m0 = -1e30f, m1 = -1e30f;
        #pragma unroll
        for (int t = 0; t < 13; ++t) {
            int mc = t * 8 + 2 * tig;
            if (mc < 98) {
                float2 b0v = *(const float2*)(gb + rb0 + mc);
                float2 b1v = *(const float2*)(gb + rb1 + mc);
                d[t][0] = d[t][0] * SCALEF + b0v.x;
                d[t][1] = d[t][1] * SCALEF + b0v.y;
                d[t][2] = d[t][2] * SCALEF + b1v.x;
                d[t][3] = d[t][3] * SCALEF + b1v.y;
                m0 = fmaxf(m0, fmaxf(d[t][0], d[t][1]));
                m1 = fmaxf(m1, fmaxf(d[t][2], d[t][3]));
            } else {
                d[t][0] = d[t][1] = d[t][2] = d[t][3] = -1e30f;
            }
        }
        m0 = fmaxf(m0, __shfl_xor_sync(~0u, m0, 1));
        m0 = fmaxf(m0, __shfl_xor_sync(~0u, m0, 2));
        m1 = fmaxf(m1, __shfl_xor_sync(~0u, m1, 1));
        m1 = fmaxf(m1, __shfl_xor_sync(~0u, m1, 2));
        float s0 = 0.f, s1 = 0.f;
        #pragma unroll
        for (int t = 0; t < 13; ++t) {
            d[t][0] = __expf(d[t][0] - m0);
            d[t][1] = __expf(d[t][1] - m0);
            d[t][2] = __expf(d[t][2] - m1);
            d[t][3] = __expf(d[t][3] - m1);
            s0 += d[t][0] + d[t][1];
            s1 += d[t][2] + d[t][3];
        }
        s0 += __shfl_xor_sync(~0u, s0, 1);
        s0 += __shfl_xor_sync(~0u, s0, 2);
        s1 += __shfl_xor_sync(~0u, s1, 1);
        s1 += __shfl_xor_sync(~0u, s1, 2);
        float rv0 = __fdividef(1.f, s0), rv1 = __fdividef(1.f, s1);

        // ---- PV: probs straight from registers (accum frag == A frag via V row-perm) ----
        float o[4][4];
        #pragma unroll
        for (int t = 0; t < 4; ++t) { o[t][0] = o[t][1] = o[t][2] = o[t][3] = 0.f; }
        {
            const float* vb = sv + h * 32 + gid;
            #pragma unroll
            for (int kb_ = 0; kb_ < 13; ++kb_) {
                // A frag: (a0,a1,a2,a3) = (P[r0,k=tig], P[r1,k=tig], P[r0,k=tig+4], P[r1,k=tig+4])
                //       = (d[kb][0], d[kb][2], d[kb][1], d[kb][3]) by the row permutation
                unsigned ph0 = t32(d[kb_][0]), ph1 = t32(d[kb_][2]);
                unsigned ph2 = t32(d[kb_][1]), ph3 = t32(d[kb_][3]);
                unsigned pl0 = t32(d[kb_][0] - __uint_as_float(ph0));
                unsigned pl1 = t32(d[kb_][2] - __uint_as_float(ph1));
                unsigned pl2 = t32(d[kb_][1] - __uint_as_float(ph2));
                unsigned pl3 = t32(d[kb_][3] - __uint_as_float(ph3));
                const float* vr0 = vb + (8 * kb_ + tig) * SV_LD;
                const float* vr1 = vr0 + 4 * SV_LD;
                #pragma unroll
                for (int t = 0; t < 4; ++t) {
                    unsigned b0 = __float_as_uint(vr0[t * 8]);
                    unsigned b1 = __float_as_uint(vr1[t * 8]);
                    mma8(o[t][0], o[t][1], o[t][2], o[t][3], ph0, ph1, ph2, ph3, b0, b1);
                    mma8(o[t][0], o[t][1], o[t][2], o[t][3], pl0, pl1, pl2, pl3, b0, b1);
                }
            }
        }
        // ---- epilogue: normalize + tf32-round into sx (attn_out) ----
        #pragma unroll
        for (int t = 0; t < 4; ++t) {
            int col = h * 32 + t * 8 + 2 * tig;
            if (r0 < 98) *(float2*)(sx + r0 * SX_LD + col) = make_float2(
                __uint_as_float(t32(o[t][0] * rv0)), __uint_as_float(t32(o[t][1] * rv0)));
            if (r1 < 98) *(float2*)(sx + r1 * SX_LD + col) = make_float2(
                __uint_as_float(t32(o[t][2] * rv1)), __uint_as_float(t32(o[t][3] * rv1)));
        }
    }
    __syncthreads();   // attn_out complete before proj

    // ============ proj: out = attn_out @ proj_w^T + b; 2 stages ============
    float* ob = out + (size_t)b * 9408;
    {
        const float4* src = (const float4*)g_wp;
        #pragma unroll
        for (int j = 0; j < 6; ++j) pf[j] = src[tid + j * 512];
        float4* dst = (float4*)smW;
        #pragma unroll
        for (int j = 0; j < 6; ++j) dst[tid + j * 512] = pf[j];
    }
    __syncthreads();
    for (int s = 0; s < 2; ++s) {
        if (s == 0) {
            const float4* src = (const float4*)(g_wp + 12288);
            #pragma unroll
            for (int j = 0; j < 3; ++j) pf[j] = src[tid + j * 512];
        }
        int njobs = (s == 0) ? 14 : 7;
        if (warp < njobs) {
            int mt = warp % 7, chL = warp / 7;
            int chID = 2 * s + chL;
            const float* ap = sx + (mt * 16 + gid) * SX_LD + tig;
            const float* wp = smW + chL * 6144 + lane * 4;
            float d[4][4];
            #pragma unroll
            for (int t = 0; t < 4; ++t) { d[t][0] = d[t][1] = d[t][2] = d[t][3] = 0.f; }
            #pragma unroll
            for (int ks = 0; ks < 12; ++ks) {
                unsigned a0 = __float_as_uint(ap[ks * 8]);
                unsigned a1 = __float_as_uint(ap[8 * SX_LD + ks * 8]);
                unsigned a2 = __float_as_uint(ap[ks * 8 + 4]);
                unsigned a3 = __float_as_uint(ap[8 * SX_LD + ks * 8 + 4]);
                #pragma unroll
                for (int t = 0; t < 4; ++t) {
                    float4 w4 = *(const float4*)(wp + ks * 512 + t * 128);
                    mma8(d[t][0], d[t][1], d[t][2], d[t][3], a0, a1, a2, a3,
                         __float_as_uint(w4.x), __float_as_uint(w4.y));
                    mma8(d[t][0], d[t][1], d[t][2], d[t][3], a0, a1, a2, a3,
                         __float_as_uint(w4.z), __float_as_uint(w4.w));
                }
            }
            int r0 = mt * 16 + gid, r1 = r0 + 8;
            int j0 = chID * 32;
            #pragma unroll
            for (int t = 0; t < 4; ++t) {
                int j = j0 + t * 8 + 2 * tig;
                float2 bb = *(const float2*)(proj_b + j);
                if (r0 < 98) *(float2*)(ob + r0 * 96 + j) =
                    make_float2(d[t][0] + bb.x, d[t][1] + bb.y);
                if (r1 < 98) *(float2*)(ob + r1 * 96 + j) =
                    make_float2(d[t][2] + bb.x, d[t][3] + bb.y);
            }
        }
        __syncthreads();
        if (s == 0) {
            float4* dst = (float4*)smW;
            #pragma unroll
            for (int j = 0; j < 3; ++j) dst[tid + j * 512] = pf[j];
            __syncthreads();
        }
    }
}

extern "C" void kernel_launch(void* const* d_in, const int* in_sizes, int n_in,
                              void* d_out, int out_size)
{
    const float* x          = (const float*)d_in[0];
    const float* qkv_w      = (const float*)d_in[1];
    const float* qkv_b      = (const float*)d_in[2];
    const float* proj_w     = (const float*)d_in[3];
    const float* proj_b     = (const float*)d_in[4];
    const float* bias_table = (const float*)d_in[5];
    const int*   rel_index  = (const int*)d_in[6];
    float* out = (float*)d_out;

    int prep_total = 18432 + 29400;
    prep_kernel<<<(prep_total + 255) / 256, 256>>>(qkv_w, proj_w, bias_table, rel_index);

    cudaFuncSetAttribute(wa3d_main, cudaFuncAttributeMaxDynamicSharedMemorySize, SMEM_BYTES);
    wa3d_main<<<4096, NT, SMEM_BYTES>>>(x, qkv_b, proj_b, out);
}

// round 15
// speedup vs baseline: 2.3699x; 1.0480x over previous
#include <cuda_runtime.h>

#define NT 512
#define SCALEF 0.17677669529663687f   // 1/sqrt(32)

// smem strides (floats). Pair-permuted K-major buffers use LD=104:
// (LD/2)=52 === 20 (mod 32) -> lane pattern gid*52+tig conflict-free for LDS.64.
#define SX_LD 104
#define SQ_LD 104
#define SK_LD 104
#define SV2_LD 208  // V pair-rows: (LD/2)=104 === 8 (mod 32) -> tig*8+gid conflict-free

// region offsets (floats)
#define OFF_SX  0        // [98][104] = 10192
#define OFF_SQ  10192    // [98][104] = 10192
#define OFF_SK  20384    // [104][104] = 10816 (rows 98..103 zeroed)
#define OFF_SV  31200    // [52 pair-rows][208] = 10816 (pair-rows 49..51 zeroed)
#define OFF_SMW 42016    // weight stage 12288
#define SMEM_FLOATS 54304
#define SMEM_BYTES (SMEM_FLOATS * 4)   // 217,216 B

__device__ float g_w1[9 * 6144];       // GEMM1 weights: frag-permuted, hi/lo split
__device__ float g_wp[3 * 6144];       // proj weights: same layout
__device__ float g_bias[3 * 98 * 100]; // bias[h][n][m], m padded to 100 (pad=0)

__device__ __forceinline__ unsigned t32(float f) {
    unsigned u; asm("cvt.rna.tf32.f32 %0, %1;" : "=r"(u) : "f"(f)); return u;
}
__device__ __forceinline__ float t32f(float f) { return __uint_as_float(t32(f)); }
__device__ __forceinline__ void mma8(float& d0, float& d1, float& d2, float& d3,
                                     unsigned a0, unsigned a1, unsigned a2, unsigned a3,
                                     unsigned b0, unsigned b1) {
    asm volatile(
        "mma.sync.aligned.m16n8k8.row.col.f32.tf32.tf32.f32 "
        "{%0,%1,%2,%3},{%4,%5,%6,%7},{%8,%9},{%0,%1,%2,%3};"
        : "+f"(d0), "+f"(d1), "+f"(d2), "+f"(d3)
        : "r"(a0), "r"(a1), "r"(a2), "r"(a3), "r"(b0), "r"(b1));
}

// ---- prep: frag-permuted pre-split weights + padded bias ----
__global__ void prep_kernel(const float* __restrict__ qkv_w,
                            const float* __restrict__ proj_w,
                            const float* __restrict__ table,
                            const int* __restrict__ rel)
{
    int i = blockIdx.x * blockDim.x + threadIdx.x;
    if (i < 13824) {
        int lane = i & 31, tk = i >> 5;
        int ch = tk / 48, rem = tk - ch * 48;
        int ks = rem >> 2, t = rem & 3;
        int gid = lane >> 2, tig = lane & 3;
        int col = ch * 32 + t * 8 + gid, c = ks * 8 + tig;
        float w0 = qkv_w[col * 96 + c], w1 = qkv_w[col * 96 + c + 4];
        float4 v;
        v.x = t32f(w0); v.y = t32f(w1);
        v.z = t32f(w0 - v.x); v.w = t32f(w1 - v.y);
        ((float4*)g_w1)[i] = v;
    } else if (i < 18432) {
        int q = i - 13824;
        int lane = q & 31, tk = q >> 5;
        int ch = tk / 48, rem = tk - ch * 48;
        int ks = rem >> 2, t = rem & 3;
        int gid = lane >> 2, tig = lane & 3;
        int col = ch * 32 + t * 8 + gid, c = ks * 8 + tig;
        float w0 = proj_w[col * 96 + c], w1 = proj_w[col * 96 + c + 4];
        float4 v;
        v.x = t32f(w0); v.y = t32f(w1);
        v.z = t32f(w0 - v.x); v.w = t32f(w1 - v.y);
        ((float4*)g_wp)[q] = v;
    } else if (i < 18432 + 29400) {
        int k = i - 18432;
        int h = k / 9800, r = k - h * 9800;
        int n = r / 100, m = r - n * 100;
        g_bias[k] = (m < 98) ? table[rel[n * 98 + m] * 3 + h] : 0.f;
    }
}

__global__ void __launch_bounds__(NT, 1)
wa3d_main(const float* __restrict__ x, const float* __restrict__ qkv_b,
          const float* __restrict__ proj_b, float* __restrict__ out)
{
    extern __shared__ float sm[];
    float* sx  = sm + OFF_SX;    // x / attn_out, tf32-rounded, COLUMN-PAIR-PERMUTED
    float* sq  = sm + OFF_SQ;    // q fp32, column-pair-permuted
    float* sk  = sm + OFF_SK;    // k tf32 bits, column-pair-permuted
    float* sv  = sm + OFF_SV;    // v tf32 bits, ROW-PAIR-INTERLEAVED [m>>1][c][m&1]
    float* smW = sm + OFF_SMW;   // weight stage

    const int b    = blockIdx.x;
    const int tid  = threadIdx.x;
    const int warp = tid >> 5, lane = tid & 31;
    const int gid  = lane >> 2;       // 0..7
    const int tig  = lane & 3;        // 0..3
    const int tig2 = tig * 2;
    const int pa   = (tig < 2) ? 4 * tig : 4 * tig - 7;  // perm of orig col 2*tig

    float4 pf[6];

    // ---- prefetch weight stage 0 ----
    {
        const float4* src = (const float4*)g_w1;
        #pragma unroll
        for (int j = 0; j < 6; ++j) pf[j] = src[tid + j * 512];
    }
    // ---- zero pad strips: sk rows 98..103, sv pair-rows 49..51 ----
    for (int i = tid; i < 624; i += NT) sk[10192 + i] = 0.f;
    for (int i = tid; i < 624; i += NT) sv[10192 + i] = 0.f;
    // ---- stage x[b], tf32-rounded, column-pair-permuted ----
    const float* xb = x + (size_t)b * 9408;
    for (int i = tid; i < 9408; i += NT) {
        int r = i / 96, c = i - r * 96;
        int q = c & 7;
        int pc = (c & ~7) | (((q & 3) << 1) | (q >> 2));
        sx[r * SX_LD + pc] = t32f(xb[i]);
    }
    // ---- store weight stage 0 ----
    {
        float4* dst = (float4*)smW;
        #pragma unroll
        for (int j = 0; j < 6; ++j) dst[tid + j * 512] = pf[j];
    }
    __syncthreads();

    // ============ GEMM1: qkv = x @ qkv_w^T + b; 5 stages ============
    for (int s = 0; s < 5; ++s) {
        if (s < 4) {
            int nf = (s == 3) ? 3 : 6;
            const float4* src = (const float4*)(g_w1 + (s + 1) * 12288);
            #pragma unroll
            for (int j = 0; j < 6; ++j) if (j < nf) pf[j] = src[tid + j * 512];
        }
        int njobs = (s < 4) ? 14 : 7;
        if (warp < njobs) {
            int mt = warp % 7, chL = warp / 7;
            int chID = 2 * s + chL;
            const float* ap = sx + (mt * 16 + gid) * SX_LD + tig2;
            const float* wp = smW + chL * 6144 + lane * 4;
            float d[4][4];
            #pragma unroll
            for (int t = 0; t < 4; ++t) { d[t][0] = d[t][1] = d[t][2] = d[t][3] = 0.f; }
            #pragma unroll
            for (int ks = 0; ks < 12; ++ks) {
                float2 aA = *(const float2*)(ap + ks * 8);
                float2 aB = *(const float2*)(ap + 8 * SX_LD + ks * 8);
                unsigned a0 = __float_as_uint(aA.x), a1 = __float_as_uint(aB.x);
                unsigned a2 = __float_as_uint(aA.y), a3 = __float_as_uint(aB.y);
                #pragma unroll
                for (int t = 0; t < 4; ++t) {
                    float4 w4 = *(const float4*)(wp + ks * 512 + t * 128);
                    mma8(d[t][0], d[t][1], d[t][2], d[t][3], a0, a1, a2, a3,
                         __float_as_uint(w4.x), __float_as_uint(w4.y));
                    mma8(d[t][0], d[t][1], d[t][2], d[t][3], a0, a1, a2, a3,
                         __float_as_uint(w4.z), __float_as_uint(w4.w));
                }
            }
            int r0 = mt * 16 + gid, r1 = r0 + 8;
            int j0 = chID * 32;
            #pragma unroll
            for (int t = 0; t < 4; ++t) {
                int jb = j0 + t * 8;
                int j  = jb + tig2;
                float2 bb = *(const float2*)(qkv_b + j);
                float v00 = d[t][0] + bb.x, v01 = d[t][1] + bb.y;
                float v10 = d[t][2] + bb.x, v11 = d[t][3] + bb.y;
                if (chID < 3) {                                   // q: fp32, col-perm
                    if (r0 < 98) { sq[r0 * SQ_LD + jb + pa] = v00; sq[r0 * SQ_LD + jb + pa + 2] = v01; }
                    if (r1 < 98) { sq[r1 * SQ_LD + jb + pa] = v10; sq[r1 * SQ_LD + jb + pa + 2] = v11; }
                } else if (chID < 6) {                            // k: tf32 bits, col-perm
                    int kb_ = jb - 96;
                    if (r0 < 98) { sk[r0 * SK_LD + kb_ + pa] = t32f(v00); sk[r0 * SK_LD + kb_ + pa + 2] = t32f(v01); }
                    if (r1 < 98) { sk[r1 * SK_LD + kb_ + pa] = t32f(v10); sk[r1 * SK_LD + kb_ + pa + 2] = t32f(v11); }
                } else {                                          // v: tf32 bits, row-pair interleave
                    int jj = j - 192;
                    if (r0 < 98) {
                        float* dst = sv + (r0 >> 1) * SV2_LD + 2 * jj + (r0 & 1);
                        dst[0] = t32f(v00); dst[2] = t32f(v01);
                    }
                    if (r1 < 98) {
                        float* dst = sv + (r1 >> 1) * SV2_LD + 2 * jj + (r1 & 1);
                        dst[0] = t32f(v10); dst[2] = t32f(v11);
                    }
                }
            }
        }
        __syncthreads();
        if (s < 4) {
            int nf = (s == 3) ? 3 : 6;
            float4* dst = (float4*)smW;
            #pragma unroll
            for (int j = 0; j < 6; ++j) if (j < nf) dst[tid + j * 512] = pf[j];
            __syncthreads();
        }
    }

    // ---- stage proj chunks 0,1 into smW now (consumed only after the
    //      post-attention __syncthreads; smW unused during attention) ----
    {
        const float4* src = (const float4*)g_wp;
        #pragma unroll
        for (int j = 0; j < 6; ++j) pf[j] = src[tid + j * 512];
        float4* dst = (float4*)smW;
        #pragma unroll
        for (int j = 0; j < 6; ++j) dst[tid + j * 512] = pf[j];
    }

    // ============ attention: fully fused, zero barriers; 21 jobs / 16 warps ============
    for (int job = warp; job < 21; job += 16) {
        int h = job / 7, mt = job - h * 7;
        int r0 = mt * 16 + gid, r1 = r0 + 8;

        // ---- scores: Q(split) x K(tf32) ----
        float d[13][4];
        #pragma unroll
        for (int t = 0; t < 13; ++t) { d[t][0] = d[t][1] = d[t][2] = d[t][3] = 0.f; }
        {
            const float* qb = sq + r0 * SQ_LD + h * 32 + tig2;
            const float* kb = sk + gid * SK_LD + h * 32 + tig2;
            #pragma unroll
            for (int c0 = 0; c0 < 32; c0 += 8) {
                float2 qA = *(const float2*)(qb + c0);
                float2 qB = *(const float2*)(qb + 8 * SQ_LD + c0);
                unsigned h0 = t32(qA.x), h1 = t32(qB.x), h2 = t32(qA.y), h3 = t32(qB.y);
                unsigned l0 = t32(qA.x - __uint_as_float(h0));
                unsigned l1 = t32(qB.x - __uint_as_float(h1));
                unsigned l2 = t32(qA.y - __uint_as_float(h2));
                unsigned l3 = t32(qB.y - __uint_as_float(h3));
                #pragma unroll
                for (int t = 0; t < 13; ++t) {
                    float2 kf = *(const float2*)(kb + (t * 8) * SK_LD + c0);
                    unsigned b0 = __float_as_uint(kf.x);
                    unsigned b1 = __float_as_uint(kf.y);
                    mma8(d[t][0], d[t][1], d[t][2], d[t][3], h0, h1, h2, h3, b0, b1);
                    mma8(d[t][0], d[t][1], d[t][2], d[t][3], l0, l1, l2, l3, b0, b1);
                }
            }
        }

        // ---- bias + mask + in-register softmax (unnormalized) ----
        const float* gb = g_bias + h * 9800;
        int rb0 = min(r0, 97) * 100, rb1 = min(r1, 97) * 100;
        float m0 = -1e30f, m1 = -1e30f;
        #pragma unroll
        for (int t = 0; t < 13; ++t) {
            int mc = t * 8 + tig2;
            if (mc < 98) {
                float2 b0v = *(const float2*)(gb + rb0 + mc);
                float2 b1v = *(const float2*)(gb + rb1 + mc);
                d[t][0] = d[t][0] * SCALEF + b0v.x;
                d[t][1] = d[t][1] * SCALEF + b0v.y;
                d[t][2] = d[t][2] * SCALEF + b1v.x;
                d[t][3] = d[t][3] * SCALEF + b1v.y;
                m0 = fmaxf(m0, fmaxf(d[t][0], d[t][1]));
                m1 = fmaxf(m1, fmaxf(d[t][2], d[t][3]));
            } else {
                d[t][0] = d[t][1] = d[t][2] = d[t][3] = -1e30f;
            }
        }
        m0 = fmaxf(m0, __shfl_xor_sync(~0u, m0, 1));
        m0 = fmaxf(m0, __shfl_xor_sync(~0u, m0, 2));
        m1 = fmaxf(m1, __shfl_xor_sync(~0u, m1, 1));
        m1 = fmaxf(m1, __shfl_xor_sync(~0u, m1, 2));
        float s0 = 0.f, s1 = 0.f;
        #pragma unroll
        for (int t = 0; t < 13; ++t) {
            d[t][0] = __expf(d[t][0] - m0);
            d[t][1] = __expf(d[t][1] - m0);
            d[t][2] = __expf(d[t][2] - m1);
            d[t][3] = __expf(d[t][3] - m1);
            s0 += d[t][0] + d[t][1];
            s1 += d[t][2] + d[t][3];
        }
        s0 += __shfl_xor_sync(~0u, s0, 1);
        s0 += __shfl_xor_sync(~0u, s0, 2);
        s1 += __shfl_xor_sync(~0u, s1, 1);
        s1 += __shfl_xor_sync(~0u, s1, 2);
        float rv0 = __fdividef(1.f, s0), rv1 = __fdividef(1.f, s1);

        // ---- PV: single-rounded P from registers; V pair-loads LDS.64 ----
        float o[4][4];
        #pragma unroll
        for (int t = 0; t < 4; ++t) { o[t][0] = o[t][1] = o[t][2] = o[t][3] = 0.f; }
        {
            const float* vb2 = sv + 2 * (h * 32 + gid);
            #pragma unroll
            for (int kb_ = 0; kb_ < 13; ++kb_) {
                unsigned ph0 = t32(d[kb_][0]), ph1 = t32(d[kb_][2]);
                unsigned ph2 = t32(d[kb_][1]), ph3 = t32(d[kb_][3]);
                const float* vp = vb2 + (4 * kb_ + tig) * SV2_LD;
                #pragma unroll
                for (int t = 0; t < 4; ++t) {
                    float2 v2 = *(const float2*)(vp + 16 * t);
                    mma8(o[t][0], o[t][1], o[t][2], o[t][3], ph0, ph1, ph2, ph3,
                         __float_as_uint(v2.x), __float_as_uint(v2.y));
                }
            }
        }
        // ---- epilogue: normalize + tf32-round + col-perm store into sx ----
        #pragma unroll
        for (int t = 0; t < 4; ++t) {
            int cb = h * 32 + t * 8;
            if (r0 < 98) {
                sx[r0 * SX_LD + cb + pa]     = t32f(o[t][0] * rv0);
                sx[r0 * SX_LD + cb + pa + 2] = t32f(o[t][1] * rv0);
            }
            if (r1 < 98) {
                sx[r1 * SX_LD + cb + pa]     = t32f(o[t][2] * rv1);
                sx[r1 * SX_LD + cb + pa + 2] = t32f(o[t][3] * rv1);
            }
        }
    }
    __syncthreads();   // attn_out complete + proj stage 0/1 visible

    // ============ proj: out = attn_out @ proj_w^T + b; 2 stages ============
    float* ob = out + (size_t)b * 9408;
    for (int s = 0; s < 2; ++s) {
        if (s == 0) {
            const float4* src = (const float4*)(g_wp + 12288);
            #pragma unroll
            for (int j = 0; j < 3; ++j) pf[j] = src[tid + j * 512];
        }
        int njobs = (s == 0) ? 14 : 7;
        if (warp < njobs) {
            int mt = warp % 7, chL = warp / 7;
            int chID = 2 * s + chL;
            const float* ap = sx + (mt * 16 + gid) * SX_LD + tig2;
            const float* wp = smW + chL * 6144 + lane * 4;
            float d[4][4];
            #pragma unroll
            for (int t = 0; t < 4; ++t) { d[t][0] = d[t][1] = d[t][2] = d[t][3] = 0.f; }
            #pragma unroll
            for (int ks = 0; ks < 12; ++ks) {
                float2 aA = *(const float2*)(ap + ks * 8);
                float2 aB = *(const float2*)(ap + 8 * SX_LD + ks * 8);
                unsigned a0 = __float_as_uint(aA.x), a1 = __float_as_uint(aB.x);
                unsigned a2 = __float_as_uint(aA.y), a3 = __float_as_uint(aB.y);
                #pragma unroll
                for (int t = 0; t < 4; ++t) {
                    float4 w4 = *(const float4*)(wp + ks * 512 + t * 128);
                    mma8(d[t][0], d[t][1], d[t][2], d[t][3], a0, a1, a2, a3,
                         __float_as_uint(w4.x), __float_as_uint(w4.y));
                    mma8(d[t][0], d[t][1], d[t][2], d[t][3], a0, a1, a2, a3,
                         __float_as_uint(w4.z), __float_as_uint(w4.w));
                }
            }
            int r0 = mt * 16 + gid, r1 = r0 + 8;
            int j0 = chID * 32;
            #pragma unroll
            for (int t = 0; t < 4; ++t) {
                int j = j0 + t * 8 + tig2;
                float2 bb = *(const float2*)(proj_b + j);
                if (r0 < 98) *(float2*)(ob + r0 * 96 + j) =
                    make_float2(d[t][0] + bb.x, d[t][1] + bb.y);
                if (r1 < 98) *(float2*)(ob + r1 * 96 + j) =
                    make_float2(d[t][2] + bb.x, d[t][3] + bb.y);
            }
        }
        __syncthreads();
        if (s == 0) {
            float4* dst = (float4*)smW;
            #pragma unroll
            for (int j = 0; j < 3; ++j) dst[tid + j * 512] = pf[j];
            __syncthreads();
        }
    }
}

extern "C" void kernel_launch(void* const* d_in, const int* in_sizes, int n_in,
                              void* d_out, int out_size)
{
    const float* x          = (const float*)d_in[0];
    const float* qkv_w      = (const float*)d_in[1];
    const float* qkv_b      = (const float*)d_in[2];
    const float* proj_w     = (const float*)d_in[3];
    const float* proj_b     = (const float*)d_in[4];
    const float* bias_table = (const float*)d_in[5];
    const int*   rel_index  = (const int*)d_in[6];
    float* out = (float*)d_out;

    int prep_total = 18432 + 29400;
    prep_kernel<<<(prep_total + 255) / 256, 256>>>(qkv_w, proj_w, bias_table, rel_index);

    cudaFuncSetAttribute(wa3d_main, cudaFuncAttributeMaxDynamicSharedMemorySize, SMEM_BYTES);
    wa3d_main<<<4096, NT, SMEM_BYTES>>>(x, qkv_b, proj_b, out);
}